// round 9
// baseline (speedup 1.0000x reference)
#include <cuda_runtime.h>

// ---------------------------------------------------------------------------
// FCHCGNN: 3-layer GCN + log_softmax.
//   CSR (counting sort by dst) -> per layer: T = X@W (f32x2 FFMA2 SGEMM,
//   8x8 thread tile, FMA-bound inner loop), warp-per-node segment reduction
//   (ILP 8, no atomics), fused self-loop+bias+relu; last layer + log_softmax.
// ---------------------------------------------------------------------------

#define NN_MAX 100000
#define EE_MAX 1600000
#define SCAN_CHUNK 1024

__device__ float g_t[(size_t)NN_MAX * 128];
__device__ float g_h[(size_t)NN_MAX * 128];
__device__ float g_dis[NN_MAX];
__device__ int   g_cnt[NN_MAX];
__device__ int   g_rowptr[NN_MAX + 1];
__device__ int   g_cursor[NN_MAX + 1];
__device__ int   g_srcs[EE_MAX];
__device__ float g_ws[EE_MAX];
__device__ int   g_bsums[128];

// --------------------------- CSR construction ------------------------------

__global__ void zero_kernel(int* __restrict__ cnt, int* __restrict__ rp,
                            int* __restrict__ cur, int n) {
    int i = blockIdx.x * blockDim.x + threadIdx.x;
    if (i < n) cnt[i] = 0;
    if (i == 0) { rp[0] = 0; cur[0] = 0; }
}

__global__ void hist_kernel(const int* __restrict__ dst, int* __restrict__ cnt, int e) {
    int i = blockIdx.x * blockDim.x + threadIdx.x;
    if (i < e) atomicAdd(&cnt[dst[i]], 1);
}

__global__ void scan1_kernel(const int* __restrict__ cnt, int* __restrict__ rp,
                             int* __restrict__ bsums, int m) {
    __shared__ int s[SCAN_CHUNK];
    int tid = threadIdx.x;
    int i = blockIdx.x * SCAN_CHUNK + tid;
    int v = (i < m) ? cnt[i] : 0;
    s[tid] = v;
    __syncthreads();
#pragma unroll
    for (int o = 1; o < SCAN_CHUNK; o <<= 1) {
        int t = 0;
        if (tid >= o) t = s[tid - o];
        __syncthreads();
        s[tid] += t;
        __syncthreads();
    }
    if (i < m) rp[i + 1] = s[tid];
    if (tid == SCAN_CHUNK - 1) bsums[blockIdx.x] = s[SCAN_CHUNK - 1];
}

__global__ void dis_kernel(const int* __restrict__ cnt, float* __restrict__ dis, int n) {
    int i = blockIdx.x * blockDim.x + threadIdx.x;
    if (i < n) dis[i] = rsqrtf((float)(cnt[i] + 1));
}

__global__ void scan3_kernel(int* __restrict__ rp, int* __restrict__ cur,
                             const int* __restrict__ bsums, int nb, int m) {
    __shared__ int sb[128];
    int t = threadIdx.x;
    if (t < 128) sb[t] = (t < nb) ? bsums[t] : 0;
    __syncthreads();
    int off = 0;
    for (int k = 0; k < blockIdx.x; k++) off += sb[k];
    int i = blockIdx.x * SCAN_CHUNK + t;
    if (i < m) {
        int v = rp[i + 1] + off;
        rp[i + 1] = v;
        cur[i + 1] = v;
    }
}

__global__ void bucket_kernel(const int* __restrict__ src, const int* __restrict__ dst,
                              const float* __restrict__ dis, int* __restrict__ cur,
                              int* __restrict__ srcs, float* __restrict__ ws, int e) {
    int i = blockIdx.x * blockDim.x + threadIdx.x;
    if (i < e) {
        int s = src[i], d = dst[i];
        int p = atomicAdd(&cur[d], 1);
        srcs[p] = s;
        ws[p] = dis[s] * dis[d];
    }
}

// ----------------------- SGEMM, f32x2, 8x8 thread tile ----------------------
// Block: 128 rows x FOUT cols, 256 threads (ty 0..15, tx 0..15).
// Thread: rows ty*8..+7, col pairs {2tx+32j}. Per kk: 4 LDS.64 X row-pairs
// (broadcast), 8 MOV dups (ALU pipe), CP2 LDS.64 W, 8*CP2 FFMA2 -> FMA-bound.

template <int FOUT>
__global__ __launch_bounds__(256, 2)
void gemm_kernel(const float* __restrict__ X, const float* __restrict__ W,
                 float* __restrict__ T, int n) {
    constexpr int KT  = 32;
    constexpr int S   = 130;          // even stride -> aligned LDS.64 row pairs
    constexpr int CP2 = FOUT / 32;    // col pairs per thread (4 or 2)
    extern __shared__ float smem[];
    float* Wt = smem;                 // [KT][FOUT]
    float* Xt = smem + KT * FOUT;     // [KT][S]  (transposed X tile)

    const int tid  = threadIdx.x;
    const int row0 = blockIdx.x * 128;
    const int ty   = tid >> 4;        // 0..15
    const int tx   = tid & 15;        // 0..15

    unsigned long long acc[8][CP2];
#pragma unroll
    for (int i = 0; i < 8; i++)
#pragma unroll
        for (int j = 0; j < CP2; j++) acc[i][j] = 0ull;

#pragma unroll 1
    for (int k0 = 0; k0 < 128; k0 += KT) {
        __syncthreads();
#pragma unroll
        for (int i = tid; i < KT * FOUT / 4; i += 256)
            ((float4*)Wt)[i] = ((const float4*)&W[(size_t)k0 * FOUT])[i];
#pragma unroll
        for (int idx = tid; idx < 128 * 8; idx += 256) {
            int r = idx >> 3, c4 = idx & 7;
            int gr = row0 + r;
            float4 v = make_float4(0.f, 0.f, 0.f, 0.f);
            if (gr < n) v = *(const float4*)&X[(size_t)gr * 128 + k0 + c4 * 4];
            Xt[(c4 * 4 + 0) * S + r] = v.x;
            Xt[(c4 * 4 + 1) * S + r] = v.y;
            Xt[(c4 * 4 + 2) * S + r] = v.z;
            Xt[(c4 * 4 + 3) * S + r] = v.w;
        }
        __syncthreads();
#pragma unroll
        for (int kk = 0; kk < KT; kk++) {
            float2 xp[4];
#pragma unroll
            for (int p = 0; p < 4; p++)
                xp[p] = *(const float2*)&Xt[kk * S + ty * 8 + 2 * p];
            unsigned long long xd[8];
#pragma unroll
            for (int p = 0; p < 4; p++) {
                asm("mov.b64 %0, {%1, %1};" : "=l"(xd[2 * p])     : "f"(xp[p].x));
                asm("mov.b64 %0, {%1, %1};" : "=l"(xd[2 * p + 1]) : "f"(xp[p].y));
            }
            unsigned long long wp[CP2];
#pragma unroll
            for (int j = 0; j < CP2; j++)
                wp[j] = *(const unsigned long long*)&Wt[kk * FOUT + 2 * tx + 32 * j];
#pragma unroll
            for (int i = 0; i < 8; i++)
#pragma unroll
                for (int j = 0; j < CP2; j++)
                    asm("fma.rn.f32x2 %0, %1, %2, %0;"
                        : "+l"(acc[i][j]) : "l"(xd[i]), "l"(wp[j]));
        }
    }

#pragma unroll
    for (int i = 0; i < 8; i++) {
        int gr = row0 + ty * 8 + i;
        if (gr < n) {
#pragma unroll
            for (int j = 0; j < CP2; j++) {
                float lo, hi;
                asm("mov.b64 {%0, %1}, %2;" : "=f"(lo), "=f"(hi) : "l"(acc[i][j]));
                *(float2*)&T[(size_t)gr * FOUT + 2 * tx + 32 * j] = make_float2(lo, hi);
            }
        }
    }
}

// ---------------------- warp-per-node segment reduction ---------------------

__device__ __forceinline__ float4 fma4(float4 v, float w, float4 a) {
    a.x = fmaf(v.x, w, a.x); a.y = fmaf(v.y, w, a.y);
    a.z = fmaf(v.z, w, a.z); a.w = fmaf(v.w, w, a.w);
    return a;
}

__global__ void aggregate128_kernel(const float* __restrict__ T, const int* __restrict__ rp,
                                    const int* __restrict__ srcs, const float* __restrict__ ws,
                                    const float* __restrict__ dis, const float* __restrict__ bias,
                                    float* __restrict__ OUT, int n) {
    int node = blockIdx.x * 8 + (threadIdx.x >> 5);
    if (node >= n) return;
    int lane = threadIdx.x & 31;
    int beg = rp[node], end = rp[node + 1];

    float4 a0 = make_float4(0.f, 0.f, 0.f, 0.f), a1 = a0, a2 = a0, a3 = a0;
    float4 a4 = a0, a5 = a0, a6 = a0, a7 = a0;
    for (int base = beg; base < end; base += 32) {
        int cnt = min(32, end - base);
        int s = 0; float w = 0.f;
        if (lane < cnt) { s = srcs[base + lane]; w = ws[base + lane]; }
        int j = 0;
        for (; j + 8 <= cnt; j += 8) {
            int   s0 = __shfl_sync(~0u, s, j),     s1 = __shfl_sync(~0u, s, j + 1);
            int   s2 = __shfl_sync(~0u, s, j + 2), s3 = __shfl_sync(~0u, s, j + 3);
            int   s4 = __shfl_sync(~0u, s, j + 4), s5 = __shfl_sync(~0u, s, j + 5);
            int   s6 = __shfl_sync(~0u, s, j + 6), s7 = __shfl_sync(~0u, s, j + 7);
            float w0 = __shfl_sync(~0u, w, j),     w1 = __shfl_sync(~0u, w, j + 1);
            float w2 = __shfl_sync(~0u, w, j + 2), w3 = __shfl_sync(~0u, w, j + 3);
            float w4 = __shfl_sync(~0u, w, j + 4), w5 = __shfl_sync(~0u, w, j + 5);
            float w6 = __shfl_sync(~0u, w, j + 6), w7 = __shfl_sync(~0u, w, j + 7);
            float4 v0 = *(const float4*)&T[(size_t)s0 * 128 + lane * 4];
            float4 v1 = *(const float4*)&T[(size_t)s1 * 128 + lane * 4];
            float4 v2 = *(const float4*)&T[(size_t)s2 * 128 + lane * 4];
            float4 v3 = *(const float4*)&T[(size_t)s3 * 128 + lane * 4];
            float4 v4 = *(const float4*)&T[(size_t)s4 * 128 + lane * 4];
            float4 v5 = *(const float4*)&T[(size_t)s5 * 128 + lane * 4];
            float4 v6 = *(const float4*)&T[(size_t)s6 * 128 + lane * 4];
            float4 v7 = *(const float4*)&T[(size_t)s7 * 128 + lane * 4];
            a0 = fma4(v0, w0, a0); a1 = fma4(v1, w1, a1);
            a2 = fma4(v2, w2, a2); a3 = fma4(v3, w3, a3);
            a4 = fma4(v4, w4, a4); a5 = fma4(v5, w5, a5);
            a6 = fma4(v6, w6, a6); a7 = fma4(v7, w7, a7);
        }
        for (; j + 4 <= cnt; j += 4) {
            int   s0 = __shfl_sync(~0u, s, j),     s1 = __shfl_sync(~0u, s, j + 1);
            int   s2 = __shfl_sync(~0u, s, j + 2), s3 = __shfl_sync(~0u, s, j + 3);
            float w0 = __shfl_sync(~0u, w, j),     w1 = __shfl_sync(~0u, w, j + 1);
            float w2 = __shfl_sync(~0u, w, j + 2), w3 = __shfl_sync(~0u, w, j + 3);
            float4 v0 = *(const float4*)&T[(size_t)s0 * 128 + lane * 4];
            float4 v1 = *(const float4*)&T[(size_t)s1 * 128 + lane * 4];
            float4 v2 = *(const float4*)&T[(size_t)s2 * 128 + lane * 4];
            float4 v3 = *(const float4*)&T[(size_t)s3 * 128 + lane * 4];
            a0 = fma4(v0, w0, a0); a1 = fma4(v1, w1, a1);
            a2 = fma4(v2, w2, a2); a3 = fma4(v3, w3, a3);
        }
        for (; j < cnt; j++) {
            int   sj = __shfl_sync(~0u, s, j);
            float wj = __shfl_sync(~0u, w, j);
            a0 = fma4(*(const float4*)&T[(size_t)sj * 128 + lane * 4], wj, a0);
        }
    }
    float dd = dis[node], sn = dd * dd;
    float4 t = *(const float4*)&T[(size_t)node * 128 + lane * 4];
    float4 b = *(const float4*)&bias[lane * 4];
    float4 o;
    o.x = fmaxf(a0.x + a1.x + a2.x + a3.x + a4.x + a5.x + a6.x + a7.x + t.x * sn + b.x, 0.f);
    o.y = fmaxf(a0.y + a1.y + a2.y + a3.y + a4.y + a5.y + a6.y + a7.y + t.y * sn + b.y, 0.f);
    o.z = fmaxf(a0.z + a1.z + a2.z + a3.z + a4.z + a5.z + a6.z + a7.z + t.z * sn + b.z, 0.f);
    o.w = fmaxf(a0.w + a1.w + a2.w + a3.w + a4.w + a5.w + a6.w + a7.w + t.w * sn + b.w, 0.f);
    *(float4*)&OUT[(size_t)node * 128 + lane * 4] = o;
}

__global__ void aggregate_lsm_kernel(const float* __restrict__ T, const int* __restrict__ rp,
                                     const int* __restrict__ srcs, const float* __restrict__ ws,
                                     const float* __restrict__ dis, const float* __restrict__ bias,
                                     float* __restrict__ OUT, int n) {
    int node = blockIdx.x * 8 + (threadIdx.x >> 5);
    if (node >= n) return;
    int lane = threadIdx.x & 31;
    int beg = rp[node], end = rp[node + 1];

    float2 a0 = make_float2(0.f, 0.f), a1 = a0, a2 = a0, a3 = a0;
    float2 a4 = a0, a5 = a0, a6 = a0, a7 = a0;
    for (int base = beg; base < end; base += 32) {
        int cnt = min(32, end - base);
        int s = 0; float w = 0.f;
        if (lane < cnt) { s = srcs[base + lane]; w = ws[base + lane]; }
        int j = 0;
        for (; j + 8 <= cnt; j += 8) {
#pragma unroll
            for (int q = 0; q < 8; q++) {
                int   sq = __shfl_sync(~0u, s, j + q);
                float wq = __shfl_sync(~0u, w, j + q);
                float2 v = *(const float2*)&T[(size_t)sq * 64 + lane * 2];
                float2* aq = (q == 0) ? &a0 : (q == 1) ? &a1 : (q == 2) ? &a2 :
                             (q == 3) ? &a3 : (q == 4) ? &a4 : (q == 5) ? &a5 :
                             (q == 6) ? &a6 : &a7;
                aq->x = fmaf(v.x, wq, aq->x);
                aq->y = fmaf(v.y, wq, aq->y);
            }
        }
        for (; j < cnt; j++) {
            int   sj = __shfl_sync(~0u, s, j);
            float wj = __shfl_sync(~0u, w, j);
            float2 v = *(const float2*)&T[(size_t)sj * 64 + lane * 2];
            a0.x = fmaf(v.x, wj, a0.x); a0.y = fmaf(v.y, wj, a0.y);
        }
    }
    float dd = dis[node], sn = dd * dd;
    float2 t = *(const float2*)&T[(size_t)node * 64 + lane * 2];
    float2 b = *(const float2*)&bias[lane * 2];
    float vx = fmaxf(a0.x + a1.x + a2.x + a3.x + a4.x + a5.x + a6.x + a7.x + t.x * sn + b.x, 0.f);
    float vy = fmaxf(a0.y + a1.y + a2.y + a3.y + a4.y + a5.y + a6.y + a7.y + t.y * sn + b.y, 0.f);

    float m = fmaxf(vx, vy);
#pragma unroll
    for (int o = 16; o; o >>= 1) m = fmaxf(m, __shfl_xor_sync(~0u, m, o));
    float sum = expf(vx - m) + expf(vy - m);
#pragma unroll
    for (int o = 16; o; o >>= 1) sum += __shfl_xor_sync(~0u, sum, o);
    float lse = m + logf(sum);
    *(float2*)&OUT[(size_t)node * 64 + lane * 2] = make_float2(vx - lse, vy - lse);
}

// --------------------------------- driver -----------------------------------

extern "C" void kernel_launch(void* const* d_in, const int* in_sizes, int n_in,
                              void* d_out, int out_size) {
    const float* x  = (const float*)d_in[0];
    const int*   ei = (const int*)d_in[1];
    const float* W0 = (const float*)d_in[2];
    const float* b0 = (const float*)d_in[3];
    const float* W1 = (const float*)d_in[4];
    const float* b1 = (const float*)d_in[5];
    const float* W2 = (const float*)d_in[6];
    const float* b2 = (const float*)d_in[7];

    const int N = in_sizes[0] / 128;
    const int E = in_sizes[1] / 2;
    const int* src = ei;
    const int* dst = ei + E;

    float *t, *h, *dis, *ws;
    int *cnt, *rp, *cur, *srcs, *bsums;
    cudaGetSymbolAddress((void**)&t,     g_t);
    cudaGetSymbolAddress((void**)&h,     g_h);
    cudaGetSymbolAddress((void**)&dis,   g_dis);
    cudaGetSymbolAddress((void**)&cnt,   g_cnt);
    cudaGetSymbolAddress((void**)&rp,    g_rowptr);
    cudaGetSymbolAddress((void**)&cur,   g_cursor);
    cudaGetSymbolAddress((void**)&srcs,  g_srcs);
    cudaGetSymbolAddress((void**)&ws,    g_ws);
    cudaGetSymbolAddress((void**)&bsums, g_bsums);

    const int smem128 = 32 * 128 * 4 + 32 * 130 * 4;  // 33024 B
    const int smem64  = 32 * 64 * 4  + 32 * 130 * 4;  // 24832 B
    cudaFuncSetAttribute(gemm_kernel<128>, cudaFuncAttributeMaxDynamicSharedMemorySize, smem128);
    cudaFuncSetAttribute(gemm_kernel<64>,  cudaFuncAttributeMaxDynamicSharedMemorySize, smem64);

    const int SB = (N + SCAN_CHUNK - 1) / SCAN_CHUNK;
    const int gblocks = (N + 127) / 128;
    const int ablocks = (N + 7) / 8;

    // launches 1-3: CSR front half
    zero_kernel<<<(N + 255) / 256, 256>>>(cnt, rp, cur, N);
    hist_kernel<<<(E + 255) / 256, 256>>>(dst, cnt, E);
    scan1_kernel<<<SB, SCAN_CHUNK>>>(cnt, rp, bsums, N);

    // launch 4 (ncu-profiled): layer-1 GEMM
    gemm_kernel<128><<<gblocks, 256, smem128>>>(x, W0, t, N);

    // CSR back half
    dis_kernel<<<(N + 255) / 256, 256>>>(cnt, dis, N);
    scan3_kernel<<<SB, SCAN_CHUNK>>>(rp, cur, bsums, SB, N);
    bucket_kernel<<<(E + 255) / 256, 256>>>(src, dst, dis, cur, srcs, ws, E);

    // layer 1 aggregate
    aggregate128_kernel<<<ablocks, 256>>>(t, rp, srcs, ws, dis, b0, h, N);

    // layer 2
    gemm_kernel<128><<<gblocks, 256, smem128>>>(h, W1, t, N);
    aggregate128_kernel<<<ablocks, 256>>>(t, rp, srcs, ws, dis, b1, h, N);

    // layer 3 + log_softmax
    gemm_kernel<64><<<gblocks, 256, smem64>>>(h, W2, t, N);
    aggregate_lsm_kernel<<<ablocks, 256>>>(t, rp, srcs, ws, dis, b2, (float*)d_out, N);
}

// round 10
// speedup vs baseline: 1.5136x; 1.5136x over previous
#include <cuda_runtime.h>
#include <cuda_fp16.h>

// ---------------------------------------------------------------------------
// FCHCGNN: 3-layer GCN + log_softmax.
//   CSR (counting sort by dst) -> per layer: T = X@W (f32x2 FFMA2 SGEMM, 4x8
//   thread tile, 512 thr, 2 blk/SM -- the R6 config), T stored as fp16;
//   warp-per-node segment reduction (ILP 4, fp16 gathers, fp32 accum),
//   fused self-loop+bias+relu; final layer fuses log_softmax.
// ---------------------------------------------------------------------------

#define NN_MAX 100000
#define EE_MAX 1600000
#define SCAN_CHUNK 1024

__device__ __half2 g_t16[(size_t)NN_MAX * 64];   // fp16 messages (128 dims max)
__device__ float   g_h[(size_t)NN_MAX * 128];
__device__ float   g_dis[NN_MAX];
__device__ int     g_cnt[NN_MAX];
__device__ int     g_rowptr[NN_MAX + 1];
__device__ int     g_cursor[NN_MAX + 1];
__device__ int     g_srcs[EE_MAX];
__device__ float   g_ws[EE_MAX];
__device__ int     g_bsums[128];

// --------------------------- CSR construction ------------------------------

__global__ void zero_kernel(int* __restrict__ cnt, int* __restrict__ rp,
                            int* __restrict__ cur, int n) {
    int i = blockIdx.x * blockDim.x + threadIdx.x;
    if (i < n) cnt[i] = 0;
    if (i == 0) { rp[0] = 0; cur[0] = 0; }
}

__global__ void hist_kernel(const int* __restrict__ dst, int* __restrict__ cnt, int e) {
    int i = blockIdx.x * blockDim.x + threadIdx.x;
    if (i < e) atomicAdd(&cnt[dst[i]], 1);
}

__global__ void scan1_kernel(const int* __restrict__ cnt, int* __restrict__ rp,
                             int* __restrict__ bsums, int m) {
    __shared__ int s[SCAN_CHUNK];
    int tid = threadIdx.x;
    int i = blockIdx.x * SCAN_CHUNK + tid;
    int v = (i < m) ? cnt[i] : 0;
    s[tid] = v;
    __syncthreads();
#pragma unroll
    for (int o = 1; o < SCAN_CHUNK; o <<= 1) {
        int t = 0;
        if (tid >= o) t = s[tid - o];
        __syncthreads();
        s[tid] += t;
        __syncthreads();
    }
    if (i < m) rp[i + 1] = s[tid];
    if (tid == SCAN_CHUNK - 1) bsums[blockIdx.x] = s[SCAN_CHUNK - 1];
}

__global__ void dis_kernel(const int* __restrict__ cnt, float* __restrict__ dis, int n) {
    int i = blockIdx.x * blockDim.x + threadIdx.x;
    if (i < n) dis[i] = rsqrtf((float)(cnt[i] + 1));
}

__global__ void scan3_kernel(int* __restrict__ rp, int* __restrict__ cur,
                             const int* __restrict__ bsums, int nb, int m) {
    __shared__ int sb[128];
    int t = threadIdx.x;
    if (t < 128) sb[t] = (t < nb) ? bsums[t] : 0;
    __syncthreads();
    int off = 0;
    for (int k = 0; k < blockIdx.x; k++) off += sb[k];
    int i = blockIdx.x * SCAN_CHUNK + t;
    if (i < m) {
        int v = rp[i + 1] + off;
        rp[i + 1] = v;
        cur[i + 1] = v;
    }
}

__global__ void bucket_kernel(const int* __restrict__ src, const int* __restrict__ dst,
                              const float* __restrict__ dis, int* __restrict__ cur,
                              int* __restrict__ srcs, float* __restrict__ ws, int e) {
    int i = blockIdx.x * blockDim.x + threadIdx.x;
    if (i < e) {
        int s = src[i], d = dst[i];
        int p = atomicAdd(&cur[d], 1);
        srcs[p] = s;
        ws[p] = dis[s] * dis[d];
    }
}

// ----------------------- SGEMM, f32x2, 4x8 thread tile ----------------------
// R6 config: 512 threads (ty 0..31, tx 0..15), thread rows ty*4..+3, col
// pairs {2tx+32j}. X staged DUPLICATED (broadcast LDS.64, no pack MOVs).
// Output written as fp16 (__half2 per col pair).

template <int FOUT>
__global__ __launch_bounds__(512, 2)
void gemm_kernel(const float* __restrict__ X, const float* __restrict__ W,
                 __half2* __restrict__ T16, int n) {
    constexpr int KT  = 32;
    constexpr int XDS = 258;
    constexpr int CP2 = FOUT / 32;    // col pairs per thread (4 or 2)
    extern __shared__ float smem[];
    float* Wt = smem;                 // [KT][FOUT]
    float* Xd = smem + KT * FOUT;     // [KT][XDS]

    const int tid  = threadIdx.x;
    const int row0 = blockIdx.x * 128;
    const int ty   = tid >> 4;
    const int tx   = tid & 15;

    unsigned long long acc[4][CP2];
#pragma unroll
    for (int i = 0; i < 4; i++)
#pragma unroll
        for (int j = 0; j < CP2; j++) acc[i][j] = 0ull;

#pragma unroll 1
    for (int k0 = 0; k0 < 128; k0 += KT) {
        __syncthreads();
#pragma unroll
        for (int i = tid; i < KT * FOUT / 4; i += 512)
            ((float4*)Wt)[i] = ((const float4*)&W[(size_t)k0 * FOUT])[i];
#pragma unroll
        for (int idx = tid; idx < 128 * 8; idx += 512) {
            int r = idx >> 3, c4 = idx & 7;
            int gr = row0 + r;
            float4 v = make_float4(0.f, 0.f, 0.f, 0.f);
            if (gr < n) v = *(const float4*)&X[(size_t)gr * 128 + k0 + c4 * 4];
            *(float2*)&Xd[(c4 * 4 + 0) * XDS + 2 * r] = make_float2(v.x, v.x);
            *(float2*)&Xd[(c4 * 4 + 1) * XDS + 2 * r] = make_float2(v.y, v.y);
            *(float2*)&Xd[(c4 * 4 + 2) * XDS + 2 * r] = make_float2(v.z, v.z);
            *(float2*)&Xd[(c4 * 4 + 3) * XDS + 2 * r] = make_float2(v.w, v.w);
        }
        __syncthreads();
#pragma unroll
        for (int kk = 0; kk < KT; kk++) {
            unsigned long long xd[4], wp[CP2];
#pragma unroll
            for (int i = 0; i < 4; i++)
                xd[i] = *(const unsigned long long*)&Xd[kk * XDS + (ty * 4 + i) * 2];
#pragma unroll
            for (int j = 0; j < CP2; j++)
                wp[j] = *(const unsigned long long*)&Wt[kk * FOUT + 2 * tx + 32 * j];
#pragma unroll
            for (int i = 0; i < 4; i++)
#pragma unroll
                for (int j = 0; j < CP2; j++)
                    asm("fma.rn.f32x2 %0, %1, %2, %0;"
                        : "+l"(acc[i][j]) : "l"(xd[i]), "l"(wp[j]));
        }
    }

#pragma unroll
    for (int i = 0; i < 4; i++) {
        int gr = row0 + ty * 4 + i;
        if (gr < n) {
#pragma unroll
            for (int j = 0; j < CP2; j++) {
                float lo, hi;
                asm("mov.b64 {%0, %1}, %2;" : "=f"(lo), "=f"(hi) : "l"(acc[i][j]));
                T16[(size_t)gr * (FOUT / 2) + tx + 16 * j] = __floats2half2_rn(lo, hi);
            }
        }
    }
}

// ---------------------- warp-per-node segment reduction ---------------------
// F=128: lane handles 4 cols (1 uint2 = 2 half2 per gather). ILP 4.

__global__ void aggregate128_kernel(const __half2* __restrict__ T16, const int* __restrict__ rp,
                                    const int* __restrict__ srcs, const float* __restrict__ ws,
                                    const float* __restrict__ dis, const float* __restrict__ bias,
                                    float* __restrict__ OUT, int n) {
    int node = blockIdx.x * 8 + (threadIdx.x >> 5);
    if (node >= n) return;
    int lane = threadIdx.x & 31;
    int beg = rp[node], end = rp[node + 1];

    float4 a0 = make_float4(0.f, 0.f, 0.f, 0.f), a1 = a0, a2 = a0, a3 = a0;
    for (int base = beg; base < end; base += 32) {
        int cnt = min(32, end - base);
        int s = 0; float w = 0.f;
        if (lane < cnt) { s = srcs[base + lane]; w = ws[base + lane]; }
        int j = 0;
        for (; j + 4 <= cnt; j += 4) {
            int   s0 = __shfl_sync(~0u, s, j),     s1 = __shfl_sync(~0u, s, j + 1);
            int   s2 = __shfl_sync(~0u, s, j + 2), s3 = __shfl_sync(~0u, s, j + 3);
            float w0 = __shfl_sync(~0u, w, j),     w1 = __shfl_sync(~0u, w, j + 1);
            float w2 = __shfl_sync(~0u, w, j + 2), w3 = __shfl_sync(~0u, w, j + 3);
            uint2 u0 = *(const uint2*)&T16[(size_t)s0 * 64 + lane * 2];
            uint2 u1 = *(const uint2*)&T16[(size_t)s1 * 64 + lane * 2];
            uint2 u2 = *(const uint2*)&T16[(size_t)s2 * 64 + lane * 2];
            uint2 u3 = *(const uint2*)&T16[(size_t)s3 * 64 + lane * 2];
            float2 p, q;
            p = __half22float2(*(__half2*)&u0.x); q = __half22float2(*(__half2*)&u0.y);
            a0.x = fmaf(p.x, w0, a0.x); a0.y = fmaf(p.y, w0, a0.y);
            a0.z = fmaf(q.x, w0, a0.z); a0.w = fmaf(q.y, w0, a0.w);
            p = __half22float2(*(__half2*)&u1.x); q = __half22float2(*(__half2*)&u1.y);
            a1.x = fmaf(p.x, w1, a1.x); a1.y = fmaf(p.y, w1, a1.y);
            a1.z = fmaf(q.x, w1, a1.z); a1.w = fmaf(q.y, w1, a1.w);
            p = __half22float2(*(__half2*)&u2.x); q = __half22float2(*(__half2*)&u2.y);
            a2.x = fmaf(p.x, w2, a2.x); a2.y = fmaf(p.y, w2, a2.y);
            a2.z = fmaf(q.x, w2, a2.z); a2.w = fmaf(q.y, w2, a2.w);
            p = __half22float2(*(__half2*)&u3.x); q = __half22float2(*(__half2*)&u3.y);
            a3.x = fmaf(p.x, w3, a3.x); a3.y = fmaf(p.y, w3, a3.y);
            a3.z = fmaf(q.x, w3, a3.z); a3.w = fmaf(q.y, w3, a3.w);
        }
        for (; j < cnt; j++) {
            int   sj = __shfl_sync(~0u, s, j);
            float wj = __shfl_sync(~0u, w, j);
            uint2 u = *(const uint2*)&T16[(size_t)sj * 64 + lane * 2];
            float2 p = __half22float2(*(__half2*)&u.x);
            float2 q = __half22float2(*(__half2*)&u.y);
            a0.x = fmaf(p.x, wj, a0.x); a0.y = fmaf(p.y, wj, a0.y);
            a0.z = fmaf(q.x, wj, a0.z); a0.w = fmaf(q.y, wj, a0.w);
        }
    }
    float dd = dis[node], sn = dd * dd;
    uint2 ut = *(const uint2*)&T16[(size_t)node * 64 + lane * 2];
    float2 tp = __half22float2(*(__half2*)&ut.x);
    float2 tq = __half22float2(*(__half2*)&ut.y);
    float4 b = *(const float4*)&bias[lane * 4];
    float4 o;
    o.x = fmaxf(a0.x + a1.x + a2.x + a3.x + tp.x * sn + b.x, 0.f);
    o.y = fmaxf(a0.y + a1.y + a2.y + a3.y + tp.y * sn + b.y, 0.f);
    o.z = fmaxf(a0.z + a1.z + a2.z + a3.z + tq.x * sn + b.z, 0.f);
    o.w = fmaxf(a0.w + a1.w + a2.w + a3.w + tq.y * sn + b.w, 0.f);
    *(float4*)&OUT[(size_t)node * 128 + lane * 4] = o;
}

// Final layer (F=64): lane handles 2 cols (1 half2 per gather), ILP 4,
// fused relu + log_softmax.
__global__ void aggregate_lsm_kernel(const __half2* __restrict__ T16, const int* __restrict__ rp,
                                     const int* __restrict__ srcs, const float* __restrict__ ws,
                                     const float* __restrict__ dis, const float* __restrict__ bias,
                                     float* __restrict__ OUT, int n) {
    int node = blockIdx.x * 8 + (threadIdx.x >> 5);
    if (node >= n) return;
    int lane = threadIdx.x & 31;
    int beg = rp[node], end = rp[node + 1];

    float2 a0 = make_float2(0.f, 0.f), a1 = a0, a2 = a0, a3 = a0;
    for (int base = beg; base < end; base += 32) {
        int cnt = min(32, end - base);
        int s = 0; float w = 0.f;
        if (lane < cnt) { s = srcs[base + lane]; w = ws[base + lane]; }
        int j = 0;
        for (; j + 4 <= cnt; j += 4) {
            int   s0 = __shfl_sync(~0u, s, j),     s1 = __shfl_sync(~0u, s, j + 1);
            int   s2 = __shfl_sync(~0u, s, j + 2), s3 = __shfl_sync(~0u, s, j + 3);
            float w0 = __shfl_sync(~0u, w, j),     w1 = __shfl_sync(~0u, w, j + 1);
            float w2 = __shfl_sync(~0u, w, j + 2), w3 = __shfl_sync(~0u, w, j + 3);
            float2 v0 = __half22float2(T16[(size_t)s0 * 32 + lane]);
            float2 v1 = __half22float2(T16[(size_t)s1 * 32 + lane]);
            float2 v2 = __half22float2(T16[(size_t)s2 * 32 + lane]);
            float2 v3 = __half22float2(T16[(size_t)s3 * 32 + lane]);
            a0.x = fmaf(v0.x, w0, a0.x); a0.y = fmaf(v0.y, w0, a0.y);
            a1.x = fmaf(v1.x, w1, a1.x); a1.y = fmaf(v1.y, w1, a1.y);
            a2.x = fmaf(v2.x, w2, a2.x); a2.y = fmaf(v2.y, w2, a2.y);
            a3.x = fmaf(v3.x, w3, a3.x); a3.y = fmaf(v3.y, w3, a3.y);
        }
        for (; j < cnt; j++) {
            int   sj = __shfl_sync(~0u, s, j);
            float wj = __shfl_sync(~0u, w, j);
            float2 v = __half22float2(T16[(size_t)sj * 32 + lane]);
            a0.x = fmaf(v.x, wj, a0.x); a0.y = fmaf(v.y, wj, a0.y);
        }
    }
    float dd = dis[node], sn = dd * dd;
    float2 t = __half22float2(T16[(size_t)node * 32 + lane]);
    float2 b = *(const float2*)&bias[lane * 2];
    float vx = fmaxf(a0.x + a1.x + a2.x + a3.x + t.x * sn + b.x, 0.f);
    float vy = fmaxf(a0.y + a1.y + a2.y + a3.y + t.y * sn + b.y, 0.f);

    float m = fmaxf(vx, vy);
#pragma unroll
    for (int o = 16; o; o >>= 1) m = fmaxf(m, __shfl_xor_sync(~0u, m, o));
    float sum = expf(vx - m) + expf(vy - m);
#pragma unroll
    for (int o = 16; o; o >>= 1) sum += __shfl_xor_sync(~0u, sum, o);
    float lse = m + logf(sum);
    *(float2*)&OUT[(size_t)node * 64 + lane * 2] = make_float2(vx - lse, vy - lse);
}

// --------------------------------- driver -----------------------------------

extern "C" void kernel_launch(void* const* d_in, const int* in_sizes, int n_in,
                              void* d_out, int out_size) {
    const float* x  = (const float*)d_in[0];
    const int*   ei = (const int*)d_in[1];
    const float* W0 = (const float*)d_in[2];
    const float* b0 = (const float*)d_in[3];
    const float* W1 = (const float*)d_in[4];
    const float* b1 = (const float*)d_in[5];
    const float* W2 = (const float*)d_in[6];
    const float* b2 = (const float*)d_in[7];

    const int N = in_sizes[0] / 128;
    const int E = in_sizes[1] / 2;
    const int* src = ei;
    const int* dst = ei + E;

    __half2* t16;
    float *h, *dis, *ws;
    int *cnt, *rp, *cur, *srcs, *bsums;
    cudaGetSymbolAddress((void**)&t16,   g_t16);
    cudaGetSymbolAddress((void**)&h,     g_h);
    cudaGetSymbolAddress((void**)&dis,   g_dis);
    cudaGetSymbolAddress((void**)&cnt,   g_cnt);
    cudaGetSymbolAddress((void**)&rp,    g_rowptr);
    cudaGetSymbolAddress((void**)&cur,   g_cursor);
    cudaGetSymbolAddress((void**)&srcs,  g_srcs);
    cudaGetSymbolAddress((void**)&ws,    g_ws);
    cudaGetSymbolAddress((void**)&bsums, g_bsums);

    const int smem128 = 32 * 128 * 4 + 32 * 258 * 4;  // 49408 B
    const int smem64  = 32 * 64 * 4  + 32 * 258 * 4;  // 41216 B
    cudaFuncSetAttribute(gemm_kernel<128>, cudaFuncAttributeMaxDynamicSharedMemorySize, smem128);
    cudaFuncSetAttribute(gemm_kernel<64>,  cudaFuncAttributeMaxDynamicSharedMemorySize, smem64);

    const int SB = (N + SCAN_CHUNK - 1) / SCAN_CHUNK;
    const int gblocks = (N + 127) / 128;
    const int ablocks = (N + 7) / 8;

    // launches 1-3: CSR front half
    zero_kernel<<<(N + 255) / 256, 256>>>(cnt, rp, cur, N);
    hist_kernel<<<(E + 255) / 256, 256>>>(dst, cnt, E);
    scan1_kernel<<<SB, SCAN_CHUNK>>>(cnt, rp, bsums, N);

    // launch 4 (ncu-profiled): layer-1 GEMM
    gemm_kernel<128><<<gblocks, 512, smem128>>>(x, W0, t16, N);

    // CSR back half
    dis_kernel<<<(N + 255) / 256, 256>>>(cnt, dis, N);
    scan3_kernel<<<SB, SCAN_CHUNK>>>(rp, cur, bsums, SB, N);
    bucket_kernel<<<(E + 255) / 256, 256>>>(src, dst, dis, cur, srcs, ws, E);

    // layer 1 aggregate
    aggregate128_kernel<<<ablocks, 256>>>(t16, rp, srcs, ws, dis, b0, h, N);

    // layer 2
    gemm_kernel<128><<<gblocks, 512, smem128>>>(h, W1, t16, N);
    aggregate128_kernel<<<ablocks, 256>>>(t16, rp, srcs, ws, dis, b1, h, N);

    // layer 3 + log_softmax
    gemm_kernel<64><<<gblocks, 512, smem64>>>(h, W2, t16, N);
    aggregate_lsm_kernel<<<ablocks, 256>>>(t16, rp, srcs, ws, dis, b2, (float*)d_out, N);
}

// round 12
// speedup vs baseline: 1.7030x; 1.1251x over previous
#include <cuda_runtime.h>
#include <cuda_fp16.h>
#include <cstdint>

// ---------------------------------------------------------------------------
// FCHCGNN: 3-layer GCN + log_softmax.
//   CSR (counting sort by dst) -> per layer: T = X@W (f32x2 FFMA2 SGEMM with
//   cp.async double-buffered staging), T stored fp16; warp-per-node segment
//   reduction (ILP 4, fp16 gathers, fp32 accum), fused self-loop+bias+relu;
//   final layer fuses log_softmax.
// ---------------------------------------------------------------------------

#define NN_MAX 100000
#define EE_MAX 1600000
#define SCAN_CHUNK 1024

__device__ __half2 g_t16[(size_t)NN_MAX * 64];
__device__ float   g_h[(size_t)NN_MAX * 128];
__device__ float   g_dis[NN_MAX];
__device__ int     g_cnt[NN_MAX];
__device__ int     g_rowptr[NN_MAX + 1];
__device__ int     g_cursor[NN_MAX + 1];
__device__ int     g_srcs[EE_MAX];
__device__ float   g_ws[EE_MAX];
__device__ int     g_bsums[128];

// --------------------------- cp.async helpers -------------------------------

__device__ __forceinline__ void cp_async16(unsigned saddr, const void* gptr, bool valid) {
    int sz = valid ? 16 : 0;
    asm volatile("cp.async.cg.shared.global [%0], [%1], 16, %2;\n"
                 :: "r"(saddr), "l"(gptr), "r"(sz));
}
__device__ __forceinline__ void cp_commit() {
    asm volatile("cp.async.commit_group;\n" ::: "memory");
}
__device__ __forceinline__ void cp_wait1() {
    asm volatile("cp.async.wait_group 1;\n" ::: "memory");
}
__device__ __forceinline__ void cp_wait0() {
    asm volatile("cp.async.wait_group 0;\n" ::: "memory");
}

// --------------------------- CSR construction ------------------------------

__global__ void zero_kernel(int* __restrict__ cnt, int* __restrict__ rp,
                            int* __restrict__ cur, int n) {
    int i = blockIdx.x * blockDim.x + threadIdx.x;
    if (i < n) cnt[i] = 0;
    if (i == 0) { rp[0] = 0; cur[0] = 0; }
}

__global__ void hist_kernel(const int* __restrict__ dst, int* __restrict__ cnt, int e) {
    int i = blockIdx.x * blockDim.x + threadIdx.x;
    if (i < e) atomicAdd(&cnt[dst[i]], 1);
}

__global__ void scan1_kernel(const int* __restrict__ cnt, int* __restrict__ rp,
                             int* __restrict__ bsums, int m) {
    __shared__ int s[SCAN_CHUNK];
    int tid = threadIdx.x;
    int i = blockIdx.x * SCAN_CHUNK + tid;
    int v = (i < m) ? cnt[i] : 0;
    s[tid] = v;
    __syncthreads();
#pragma unroll
    for (int o = 1; o < SCAN_CHUNK; o <<= 1) {
        int t = 0;
        if (tid >= o) t = s[tid - o];
        __syncthreads();
        s[tid] += t;
        __syncthreads();
    }
    if (i < m) rp[i + 1] = s[tid];
    if (tid == SCAN_CHUNK - 1) bsums[blockIdx.x] = s[SCAN_CHUNK - 1];
}

__global__ void dis_kernel(const int* __restrict__ cnt, float* __restrict__ dis, int n) {
    int i = blockIdx.x * blockDim.x + threadIdx.x;
    if (i < n) dis[i] = rsqrtf((float)(cnt[i] + 1));
}

__global__ void scan3_kernel(int* __restrict__ rp, int* __restrict__ cur,
                             const int* __restrict__ bsums, int nb, int m) {
    __shared__ int sb[128];
    int t = threadIdx.x;
    if (t < 128) sb[t] = (t < nb) ? bsums[t] : 0;
    __syncthreads();
    int off = 0;
    for (int k = 0; k < blockIdx.x; k++) off += sb[k];
    int i = blockIdx.x * SCAN_CHUNK + t;
    if (i < m) {
        int v = rp[i + 1] + off;
        rp[i + 1] = v;
        cur[i + 1] = v;
    }
}

__global__ void bucket_kernel(const int* __restrict__ src, const int* __restrict__ dst,
                              const float* __restrict__ dis, int* __restrict__ cur,
                              int* __restrict__ srcs, float* __restrict__ ws, int e) {
    int i = blockIdx.x * blockDim.x + threadIdx.x;
    if (i < e) {
        int s = src[i], d = dst[i];
        int p = atomicAdd(&cur[d], 1);
        srcs[p] = s;
        ws[p] = dis[s] * dis[d];
    }
}

// ------------- SGEMM, f32x2, 4x8 tile, cp.async double buffering ------------
// Block: 128 rows x FOUT cols, 512 threads (ty 0..31, tx 0..15).
// Smem per buffer: Wt[KT][FOUT] (raw copy) + Xs[128][36] (row-major, padded,
// 16B-aligned rows). Tile t+1 prefetched via cp.async while tile t computes.

template <int FOUT>
__global__ __launch_bounds__(512, 2)
void gemm_kernel(const float* __restrict__ X, const float* __restrict__ W,
                 __half2* __restrict__ T16, int n) {
    constexpr int KT   = 32;
    constexpr int XS   = 36;                       // words/row (144B, 16B-aligned)
    constexpr int CP2  = FOUT / 32;                // col pairs per thread (4 or 2)
    constexpr int WCH  = KT * FOUT / 4;            // W 16B-chunks per tile
    constexpr int BUFW = KT * FOUT + 128 * XS;     // words per buffer
    extern __shared__ float smem[];
    // buffer b: Wt = smem + b*BUFW, Xs = smem + b*BUFW + KT*FOUT

    const int tid  = threadIdx.x;
    const int row0 = blockIdx.x * 128;
    const int ty   = tid >> 4;
    const int tx   = tid & 15;

    unsigned sbase = (unsigned)__cvta_generic_to_shared(smem);

    auto prefetch = [&](int t) {
        int buf = t & 1;
        int k0  = t * KT;
        unsigned wt = sbase + (unsigned)(buf * BUFW) * 4u;
        unsigned xs = wt + (unsigned)(KT * FOUT) * 4u;
        // W tile: straight copy of rows k0..k0+KT
        const float* wg = W + (size_t)k0 * FOUT;
#pragma unroll
        for (int c = tid; c < WCH; c += 512)
            cp_async16(wt + (unsigned)c * 16u, wg + c * 4, true);
        // X tile: 128 rows x 8 chunks, row-major padded
#pragma unroll
        for (int c = tid; c < 1024; c += 512) {
            int r = c >> 3, col = c & 7;
            int gr = row0 + r;
            cp_async16(xs + (unsigned)(r * XS + col * 4) * 4u,
                       X + (size_t)gr * 128 + k0 + col * 4, gr < n);
        }
        cp_commit();
    };

    unsigned long long acc[4][CP2];
#pragma unroll
    for (int i = 0; i < 4; i++)
#pragma unroll
        for (int j = 0; j < CP2; j++) acc[i][j] = 0ull;

    prefetch(0);

#pragma unroll 1
    for (int t = 0; t < 4; t++) {
        if (t < 3) { prefetch(t + 1); cp_wait1(); }
        else       { cp_wait0(); }
        __syncthreads();

        const float* Wt = smem + (t & 1) * BUFW;
        const float* Xs = Wt + KT * FOUT;

#pragma unroll
        for (int kk = 0; kk < KT; kk++) {
            float xv[4];
#pragma unroll
            for (int i = 0; i < 4; i++)
                xv[i] = Xs[(ty * 4 + i) * XS + kk];
            unsigned long long xd[4];
#pragma unroll
            for (int i = 0; i < 4; i++)
                asm("mov.b64 %0, {%1, %1};" : "=l"(xd[i]) : "f"(xv[i]));
            unsigned long long wp[CP2];
#pragma unroll
            for (int j = 0; j < CP2; j++)
                wp[j] = *(const unsigned long long*)&Wt[kk * FOUT + 2 * tx + 32 * j];
#pragma unroll
            for (int i = 0; i < 4; i++)
#pragma unroll
                for (int j = 0; j < CP2; j++)
                    asm("fma.rn.f32x2 %0, %1, %2, %0;"
                        : "+l"(acc[i][j]) : "l"(xd[i]), "l"(wp[j]));
        }
        __syncthreads();   // protect buffer (t&1) before prefetch(t+2) writes it
    }

#pragma unroll
    for (int i = 0; i < 4; i++) {
        int gr = row0 + ty * 4 + i;
        if (gr < n) {
#pragma unroll
            for (int j = 0; j < CP2; j++) {
                float lo, hi;
                asm("mov.b64 {%0, %1}, %2;" : "=f"(lo), "=f"(hi) : "l"(acc[i][j]));
                T16[(size_t)gr * (FOUT / 2) + tx + 16 * j] = __floats2half2_rn(lo, hi);
            }
        }
    }
}

// ---------------------- warp-per-node segment reduction ---------------------

__global__ void aggregate128_kernel(const __half2* __restrict__ T16, const int* __restrict__ rp,
                                    const int* __restrict__ srcs, const float* __restrict__ ws,
                                    const float* __restrict__ dis, const float* __restrict__ bias,
                                    float* __restrict__ OUT, int n) {
    int node = blockIdx.x * 8 + (threadIdx.x >> 5);
    if (node >= n) return;
    int lane = threadIdx.x & 31;
    int beg = rp[node], end = rp[node + 1];

    float4 a0 = make_float4(0.f, 0.f, 0.f, 0.f), a1 = a0, a2 = a0, a3 = a0;
    for (int base = beg; base < end; base += 32) {
        int cnt = min(32, end - base);
        int s = 0; float w = 0.f;
        if (lane < cnt) { s = srcs[base + lane]; w = ws[base + lane]; }
        int j = 0;
        for (; j + 4 <= cnt; j += 4) {
            int   s0 = __shfl_sync(~0u, s, j),     s1 = __shfl_sync(~0u, s, j + 1);
            int   s2 = __shfl_sync(~0u, s, j + 2), s3 = __shfl_sync(~0u, s, j + 3);
            float w0 = __shfl_sync(~0u, w, j),     w1 = __shfl_sync(~0u, w, j + 1);
            float w2 = __shfl_sync(~0u, w, j + 2), w3 = __shfl_sync(~0u, w, j + 3);
            uint2 u0 = *(const uint2*)&T16[(size_t)s0 * 64 + lane * 2];
            uint2 u1 = *(const uint2*)&T16[(size_t)s1 * 64 + lane * 2];
            uint2 u2 = *(const uint2*)&T16[(size_t)s2 * 64 + lane * 2];
            uint2 u3 = *(const uint2*)&T16[(size_t)s3 * 64 + lane * 2];
            float2 p, q;
            p = __half22float2(*(__half2*)&u0.x); q = __half22float2(*(__half2*)&u0.y);
            a0.x = fmaf(p.x, w0, a0.x); a0.y = fmaf(p.y, w0, a0.y);
            a0.z = fmaf(q.x, w0, a0.z); a0.w = fmaf(q.y, w0, a0.w);
            p = __half22float2(*(__half2*)&u1.x); q = __half22float2(*(__half2*)&u1.y);
            a1.x = fmaf(p.x, w1, a1.x); a1.y = fmaf(p.y, w1, a1.y);
            a1.z = fmaf(q.x, w1, a1.z); a1.w = fmaf(q.y, w1, a1.w);
            p = __half22float2(*(__half2*)&u2.x); q = __half22float2(*(__half2*)&u2.y);
            a2.x = fmaf(p.x, w2, a2.x); a2.y = fmaf(p.y, w2, a2.y);
            a2.z = fmaf(q.x, w2, a2.z); a2.w = fmaf(q.y, w2, a2.w);
            p = __half22float2(*(__half2*)&u3.x); q = __half22float2(*(__half2*)&u3.y);
            a3.x = fmaf(p.x, w3, a3.x); a3.y = fmaf(p.y, w3, a3.y);
            a3.z = fmaf(q.x, w3, a3.z); a3.w = fmaf(q.y, w3, a3.w);
        }
        for (; j < cnt; j++) {
            int   sj = __shfl_sync(~0u, s, j);
            float wj = __shfl_sync(~0u, w, j);
            uint2 u = *(const uint2*)&T16[(size_t)sj * 64 + lane * 2];
            float2 p = __half22float2(*(__half2*)&u.x);
            float2 q = __half22float2(*(__half2*)&u.y);
            a0.x = fmaf(p.x, wj, a0.x); a0.y = fmaf(p.y, wj, a0.y);
            a0.z = fmaf(q.x, wj, a0.z); a0.w = fmaf(q.y, wj, a0.w);
        }
    }
    float dd = dis[node], sn = dd * dd;
    uint2 ut = *(const uint2*)&T16[(size_t)node * 64 + lane * 2];
    float2 tp = __half22float2(*(__half2*)&ut.x);
    float2 tq = __half22float2(*(__half2*)&ut.y);
    float4 b = *(const float4*)&bias[lane * 4];
    float4 o;
    o.x = fmaxf(a0.x + a1.x + a2.x + a3.x + tp.x * sn + b.x, 0.f);
    o.y = fmaxf(a0.y + a1.y + a2.y + a3.y + tp.y * sn + b.y, 0.f);
    o.z = fmaxf(a0.z + a1.z + a2.z + a3.z + tq.x * sn + b.z, 0.f);
    o.w = fmaxf(a0.w + a1.w + a2.w + a3.w + tq.y * sn + b.w, 0.f);
    *(float4*)&OUT[(size_t)node * 128 + lane * 4] = o;
}

__global__ void aggregate_lsm_kernel(const __half2* __restrict__ T16, const int* __restrict__ rp,
                                     const int* __restrict__ srcs, const float* __restrict__ ws,
                                     const float* __restrict__ dis, const float* __restrict__ bias,
                                     float* __restrict__ OUT, int n) {
    int node = blockIdx.x * 8 + (threadIdx.x >> 5);
    if (node >= n) return;
    int lane = threadIdx.x & 31;
    int beg = rp[node], end = rp[node + 1];

    float2 a0 = make_float2(0.f, 0.f), a1 = a0, a2 = a0, a3 = a0;
    for (int base = beg; base < end; base += 32) {
        int cnt = min(32, end - base);
        int s = 0; float w = 0.f;
        if (lane < cnt) { s = srcs[base + lane]; w = ws[base + lane]; }
        int j = 0;
        for (; j + 4 <= cnt; j += 4) {
            int   s0 = __shfl_sync(~0u, s, j),     s1 = __shfl_sync(~0u, s, j + 1);
            int   s2 = __shfl_sync(~0u, s, j + 2), s3 = __shfl_sync(~0u, s, j + 3);
            float w0 = __shfl_sync(~0u, w, j),     w1 = __shfl_sync(~0u, w, j + 1);
            float w2 = __shfl_sync(~0u, w, j + 2), w3 = __shfl_sync(~0u, w, j + 3);
            float2 v0 = __half22float2(T16[(size_t)s0 * 32 + lane]);
            float2 v1 = __half22float2(T16[(size_t)s1 * 32 + lane]);
            float2 v2 = __half22float2(T16[(size_t)s2 * 32 + lane]);
            float2 v3 = __half22float2(T16[(size_t)s3 * 32 + lane]);
            a0.x = fmaf(v0.x, w0, a0.x); a0.y = fmaf(v0.y, w0, a0.y);
            a1.x = fmaf(v1.x, w1, a1.x); a1.y = fmaf(v1.y, w1, a1.y);
            a2.x = fmaf(v2.x, w2, a2.x); a2.y = fmaf(v2.y, w2, a2.y);
            a3.x = fmaf(v3.x, w3, a3.x); a3.y = fmaf(v3.y, w3, a3.y);
        }
        for (; j < cnt; j++) {
            int   sj = __shfl_sync(~0u, s, j);
            float wj = __shfl_sync(~0u, w, j);
            float2 v = __half22float2(T16[(size_t)sj * 32 + lane]);
            a0.x = fmaf(v.x, wj, a0.x); a0.y = fmaf(v.y, wj, a0.y);
        }
    }
    float dd = dis[node], sn = dd * dd;
    float2 t = __half22float2(T16[(size_t)node * 32 + lane]);
    float2 b = *(const float2*)&bias[lane * 2];
    float vx = fmaxf(a0.x + a1.x + a2.x + a3.x + t.x * sn + b.x, 0.f);
    float vy = fmaxf(a0.y + a1.y + a2.y + a3.y + t.y * sn + b.y, 0.f);

    float m = fmaxf(vx, vy);
#pragma unroll
    for (int o = 16; o; o >>= 1) m = fmaxf(m, __shfl_xor_sync(~0u, m, o));
    float sum = expf(vx - m) + expf(vy - m);
#pragma unroll
    for (int o = 16; o; o >>= 1) sum += __shfl_xor_sync(~0u, sum, o);
    float lse = m + logf(sum);
    *(float2*)&OUT[(size_t)node * 64 + lane * 2] = make_float2(vx - lse, vy - lse);
}

// --------------------------------- driver -----------------------------------

extern "C" void kernel_launch(void* const* d_in, const int* in_sizes, int n_in,
                              void* d_out, int out_size) {
    const float* x  = (const float*)d_in[0];
    const int*   ei = (const int*)d_in[1];
    const float* W0 = (const float*)d_in[2];
    const float* b0 = (const float*)d_in[3];
    const float* W1 = (const float*)d_in[4];
    const float* b1 = (const float*)d_in[5];
    const float* W2 = (const float*)d_in[6];
    const float* b2 = (const float*)d_in[7];

    const int N = in_sizes[0] / 128;
    const int E = in_sizes[1] / 2;
    const int* src = ei;
    const int* dst = ei + E;

    __half2* t16;
    float *h, *dis, *ws;
    int *cnt, *rp, *cur, *srcs, *bsums;
    cudaGetSymbolAddress((void**)&t16,   g_t16);
    cudaGetSymbolAddress((void**)&h,     g_h);
    cudaGetSymbolAddress((void**)&dis,   g_dis);
    cudaGetSymbolAddress((void**)&cnt,   g_cnt);
    cudaGetSymbolAddress((void**)&rp,    g_rowptr);
    cudaGetSymbolAddress((void**)&cur,   g_cursor);
    cudaGetSymbolAddress((void**)&srcs,  g_srcs);
    cudaGetSymbolAddress((void**)&ws,    g_ws);
    cudaGetSymbolAddress((void**)&bsums, g_bsums);

    // double-buffered smem: 2 * (KT*FOUT + 128*36) words
    const int smem128 = 2 * (32 * 128 + 128 * 36) * 4;  // 69632 B
    const int smem64  = 2 * (32 * 64  + 128 * 36) * 4;  // 53248 B
    cudaFuncSetAttribute(gemm_kernel<128>, cudaFuncAttributeMaxDynamicSharedMemorySize, smem128);
    cudaFuncSetAttribute(gemm_kernel<64>,  cudaFuncAttributeMaxDynamicSharedMemorySize, smem64);

    const int SB = (N + SCAN_CHUNK - 1) / SCAN_CHUNK;
    const int gblocks = (N + 127) / 128;
    const int ablocks = (N + 7) / 8;

    // launches 1-3: CSR front half
    zero_kernel<<<(N + 255) / 256, 256>>>(cnt, rp, cur, N);
    hist_kernel<<<(E + 255) / 256, 256>>>(dst, cnt, E);
    scan1_kernel<<<SB, SCAN_CHUNK>>>(cnt, rp, bsums, N);

    // launch 4 (ncu-profiled): layer-1 GEMM
    gemm_kernel<128><<<gblocks, 512, smem128>>>(x, W0, t16, N);

    // CSR back half
    dis_kernel<<<(N + 255) / 256, 256>>>(cnt, dis, N);
    scan3_kernel<<<SB, SCAN_CHUNK>>>(rp, cur, bsums, SB, N);
    bucket_kernel<<<(E + 255) / 256, 256>>>(src, dst, dis, cur, srcs, ws, E);

    // layer 1 aggregate
    aggregate128_kernel<<<ablocks, 256>>>(t16, rp, srcs, ws, dis, b0, h, N);

    // layer 2
    gemm_kernel<128><<<gblocks, 512, smem128>>>(h, W1, t16, N);
    aggregate128_kernel<<<ablocks, 256>>>(t16, rp, srcs, ws, dis, b1, h, N);

    // layer 3 + log_softmax
    gemm_kernel<64><<<gblocks, 512, smem64>>>(h, W2, t16, N);
    aggregate_lsm_kernel<<<ablocks, 256>>>(t16, rp, srcs, ws, dis, b2, (float*)d_out, N);
}

// round 13
// speedup vs baseline: 2.2083x; 1.2967x over previous
#include <cuda_runtime.h>
#include <cuda_fp16.h>
#include <cstdint>

// ---------------------------------------------------------------------------
// FCHCGNN: 3-layer GCN + log_softmax.
//   CSR (counting sort by dst) -> per layer: T = X@W on TENSOR CORES
//   (mma.sync m16n8k16 f16xf16+f32, K=128 smem-resident, ldmatrix), T fp16;
//   warp-per-node segment reduction (ILP 4, fp16 gathers, fp32 accum),
//   h stored fp16 (only feeds next GEMM); final layer fuses log_softmax.
// ---------------------------------------------------------------------------

#define NN_MAX 100000
#define EE_MAX 1600000
#define SCAN_CHUNK 1024

__device__ __half2 g_t16[(size_t)NN_MAX * 64];
__device__ __half2 g_h16[(size_t)NN_MAX * 64];
__device__ float   g_dis[NN_MAX];
__device__ int     g_cnt[NN_MAX];
__device__ int     g_rowptr[NN_MAX + 1];
__device__ int     g_cursor[NN_MAX + 1];
__device__ int     g_srcs[EE_MAX];
__device__ float   g_ws[EE_MAX];
__device__ int     g_bsums[128];

// --------------------------- CSR construction ------------------------------

__global__ void zero_kernel(int* __restrict__ cnt, int* __restrict__ rp,
                            int* __restrict__ cur, int n) {
    int i = blockIdx.x * blockDim.x + threadIdx.x;
    if (i < n) cnt[i] = 0;
    if (i == 0) { rp[0] = 0; cur[0] = 0; }
}

__global__ void hist_kernel(const int* __restrict__ dst, int* __restrict__ cnt, int e) {
    int i = blockIdx.x * blockDim.x + threadIdx.x;
    if (i < e) atomicAdd(&cnt[dst[i]], 1);
}

__global__ void scan1_kernel(const int* __restrict__ cnt, int* __restrict__ rp,
                             int* __restrict__ bsums, int m) {
    __shared__ int s[SCAN_CHUNK];
    int tid = threadIdx.x;
    int i = blockIdx.x * SCAN_CHUNK + tid;
    int v = (i < m) ? cnt[i] : 0;
    s[tid] = v;
    __syncthreads();
#pragma unroll
    for (int o = 1; o < SCAN_CHUNK; o <<= 1) {
        int t = 0;
        if (tid >= o) t = s[tid - o];
        __syncthreads();
        s[tid] += t;
        __syncthreads();
    }
    if (i < m) rp[i + 1] = s[tid];
    if (tid == SCAN_CHUNK - 1) bsums[blockIdx.x] = s[SCAN_CHUNK - 1];
}

__global__ void dis_kernel(const int* __restrict__ cnt, float* __restrict__ dis, int n) {
    int i = blockIdx.x * blockDim.x + threadIdx.x;
    if (i < n) dis[i] = rsqrtf((float)(cnt[i] + 1));
}

__global__ void scan3_kernel(int* __restrict__ rp, int* __restrict__ cur,
                             const int* __restrict__ bsums, int nb, int m) {
    __shared__ int sb[128];
    int t = threadIdx.x;
    if (t < 128) sb[t] = (t < nb) ? bsums[t] : 0;
    __syncthreads();
    int off = 0;
    for (int k = 0; k < blockIdx.x; k++) off += sb[k];
    int i = blockIdx.x * SCAN_CHUNK + t;
    if (i < m) {
        int v = rp[i + 1] + off;
        rp[i + 1] = v;
        cur[i + 1] = v;
    }
}

__global__ void bucket_kernel(const int* __restrict__ src, const int* __restrict__ dst,
                              const float* __restrict__ dis, int* __restrict__ cur,
                              int* __restrict__ srcs, float* __restrict__ ws, int e) {
    int i = blockIdx.x * blockDim.x + threadIdx.x;
    if (i < e) {
        int s = src[i], d = dst[i];
        int p = atomicAdd(&cur[d], 1);
        srcs[p] = s;
        ws[p] = dis[s] * dis[d];
    }
}

// ----------------------- tensor-core GEMM (HMMA) ----------------------------
// Block: 128 rows x 64 cols, 256 threads = 8 warps (4 row-groups x 2 col-grps).
// K = 128 fully staged in smem as fp16. A via ldmatrix.x4, B via
// ldmatrix.x4.trans; row strides 136/72 halves -> conflict-free.
// Accumulate fp32, write T as __half2.

__device__ __forceinline__ void ldsm_x4(unsigned& r0, unsigned& r1, unsigned& r2,
                                        unsigned& r3, unsigned addr) {
    asm volatile("ldmatrix.sync.aligned.m8n8.x4.shared.b16 {%0,%1,%2,%3}, [%4];"
                 : "=r"(r0), "=r"(r1), "=r"(r2), "=r"(r3) : "r"(addr));
}
__device__ __forceinline__ void ldsm_x4t(unsigned& r0, unsigned& r1, unsigned& r2,
                                         unsigned& r3, unsigned addr) {
    asm volatile("ldmatrix.sync.aligned.m8n8.x4.trans.shared.b16 {%0,%1,%2,%3}, [%4];"
                 : "=r"(r0), "=r"(r1), "=r"(r2), "=r"(r3) : "r"(addr));
}
__device__ __forceinline__ void mma16816(float* c, unsigned a0, unsigned a1,
                                         unsigned a2, unsigned a3,
                                         unsigned b0, unsigned b1) {
    asm volatile("mma.sync.aligned.m16n8k16.row.col.f32.f16.f16.f32 "
                 "{%0,%1,%2,%3}, {%4,%5,%6,%7}, {%8,%9}, {%0,%1,%2,%3};"
                 : "+f"(c[0]), "+f"(c[1]), "+f"(c[2]), "+f"(c[3])
                 : "r"(a0), "r"(a1), "r"(a2), "r"(a3), "r"(b0), "r"(b1));
}

template <typename InT, int FOUT>
__global__ __launch_bounds__(256)
void gemm_tc(const InT* __restrict__ X, const float* __restrict__ W,
             __half2* __restrict__ T16, int n) {
    constexpr int AS = 136;   // X smem row stride (halves): 272B = 68 words ≡ 4 mod 32
    constexpr int BS = 72;    // W smem row stride (halves): 144B = 36 words ≡ 4 mod 32
    extern __shared__ __half sm[];
    __half* Xs  = sm;                  // [128][AS]
    __half* Wsm = sm + 128 * AS;       // [128][BS] (64 cols used)

    const int tid  = threadIdx.x;
    const int row0 = blockIdx.x * 128;
    const int col0 = blockIdx.y * 64;

    // ---- stage X (fp32 -> fp16 convert, or fp16 raw copy) ----
    if constexpr (sizeof(InT) == 4) {
        // 128 rows x 32 float4 chunks
        for (int i = tid; i < 128 * 32; i += 256) {
            int r = i >> 5, c = i & 31;
            int gr = row0 + r;
            float4 v = make_float4(0.f, 0.f, 0.f, 0.f);
            if (gr < n) v = *(const float4*)&X[(size_t)gr * 128 + c * 4];
            __half2* p = (__half2*)&Xs[r * AS + c * 4];
            p[0] = __floats2half2_rn(v.x, v.y);
            p[1] = __floats2half2_rn(v.z, v.w);
        }
    } else {
        // 128 rows x 16 uint4 chunks (8 halves each)
        for (int i = tid; i < 128 * 16; i += 256) {
            int r = i >> 4, c = i & 15;
            int gr = row0 + r;
            uint4 v = make_uint4(0u, 0u, 0u, 0u);
            if (gr < n) v = *(const uint4*)&X[(size_t)gr * 128 + c * 8];
            *(uint4*)&Xs[r * AS + c * 8] = v;
        }
    }
    // ---- stage W cols col0..col0+63 (fp32 -> fp16) ----
    for (int i = tid; i < 128 * 16; i += 256) {
        int k = i >> 4, c = i & 15;
        float4 v = *(const float4*)&W[(size_t)k * FOUT + col0 + c * 4];
        __half2* p = (__half2*)&Wsm[k * BS + c * 4];
        p[0] = __floats2half2_rn(v.x, v.y);
        p[1] = __floats2half2_rn(v.z, v.w);
    }
    __syncthreads();

    const int w    = tid >> 5;
    const int lane = tid & 31;
    const int wr   = w >> 1;    // 0..3 : rows 32*wr..+31
    const int wc   = w & 1;     // 0..1 : cols 32*wc..+31

    unsigned xb = (unsigned)__cvta_generic_to_shared(Xs);
    unsigned wb = (unsigned)__cvta_generic_to_shared(Wsm);

    float c[2][4][4];
#pragma unroll
    for (int ma = 0; ma < 2; ma++)
#pragma unroll
        for (int na = 0; na < 4; na++)
#pragma unroll
            for (int q = 0; q < 4; q++) c[ma][na][q] = 0.f;

    const int lrow = lane & 15;
    const int lhi  = (lane >> 4) << 3;   // 0 or 8

#pragma unroll
    for (int k0 = 0; k0 < 8; k0++) {    // k16 steps
        unsigned a[2][4];
#pragma unroll
        for (int ma = 0; ma < 2; ma++) {
            unsigned addr = xb + (unsigned)((32 * wr + 16 * ma + lrow) * AS
                                            + k0 * 16 + lhi) * 2u;
            ldsm_x4(a[ma][0], a[ma][1], a[ma][2], a[ma][3], addr);
        }
        unsigned b[2][4];
#pragma unroll
        for (int np = 0; np < 2; np++) {
            unsigned addr = wb + (unsigned)((k0 * 16 + lrow) * BS
                                            + 32 * wc + 16 * np + lhi) * 2u;
            ldsm_x4t(b[np][0], b[np][1], b[np][2], b[np][3], addr);
        }
#pragma unroll
        for (int ma = 0; ma < 2; ma++)
#pragma unroll
            for (int np = 0; np < 2; np++)
#pragma unroll
                for (int nb = 0; nb < 2; nb++)
                    mma16816(c[ma][2 * np + nb], a[ma][0], a[ma][1], a[ma][2],
                             a[ma][3], b[np][2 * nb], b[np][2 * nb + 1]);
    }

    // ---- epilogue: write fp16 ----
    const int g = lane >> 2;            // 0..7
    const int lc = lane & 3;
#pragma unroll
    for (int ma = 0; ma < 2; ma++) {
        int r0 = row0 + 32 * wr + 16 * ma + g;
#pragma unroll
        for (int na = 0; na < 4; na++) {
            int h2i = (col0 >> 1) + 16 * wc + 4 * na + lc;
            if (r0 < n)
                T16[(size_t)r0 * (FOUT / 2) + h2i] =
                    __floats2half2_rn(c[ma][na][0], c[ma][na][1]);
            if (r0 + 8 < n)
                T16[(size_t)(r0 + 8) * (FOUT / 2) + h2i] =
                    __floats2half2_rn(c[ma][na][2], c[ma][na][3]);
        }
    }
}

// ---------------------- warp-per-node segment reduction ---------------------

__global__ void aggregate128_kernel(const __half2* __restrict__ T16, const int* __restrict__ rp,
                                    const int* __restrict__ srcs, const float* __restrict__ ws,
                                    const float* __restrict__ dis, const float* __restrict__ bias,
                                    __half2* __restrict__ OUT, int n) {
    int node = blockIdx.x * 8 + (threadIdx.x >> 5);
    if (node >= n) return;
    int lane = threadIdx.x & 31;
    int beg = rp[node], end = rp[node + 1];

    float4 a0 = make_float4(0.f, 0.f, 0.f, 0.f), a1 = a0, a2 = a0, a3 = a0;
    for (int base = beg; base < end; base += 32) {
        int cnt = min(32, end - base);
        int s = 0; float w = 0.f;
        if (lane < cnt) { s = srcs[base + lane]; w = ws[base + lane]; }
        int j = 0;
        for (; j + 4 <= cnt; j += 4) {
            int   s0 = __shfl_sync(~0u, s, j),     s1 = __shfl_sync(~0u, s, j + 1);
            int   s2 = __shfl_sync(~0u, s, j + 2), s3 = __shfl_sync(~0u, s, j + 3);
            float w0 = __shfl_sync(~0u, w, j),     w1 = __shfl_sync(~0u, w, j + 1);
            float w2 = __shfl_sync(~0u, w, j + 2), w3 = __shfl_sync(~0u, w, j + 3);
            uint2 u0 = *(const uint2*)&T16[(size_t)s0 * 64 + lane * 2];
            uint2 u1 = *(const uint2*)&T16[(size_t)s1 * 64 + lane * 2];
            uint2 u2 = *(const uint2*)&T16[(size_t)s2 * 64 + lane * 2];
            uint2 u3 = *(const uint2*)&T16[(size_t)s3 * 64 + lane * 2];
            float2 p, q;
            p = __half22float2(*(__half2*)&u0.x); q = __half22float2(*(__half2*)&u0.y);
            a0.x = fmaf(p.x, w0, a0.x); a0.y = fmaf(p.y, w0, a0.y);
            a0.z = fmaf(q.x, w0, a0.z); a0.w = fmaf(q.y, w0, a0.w);
            p = __half22float2(*(__half2*)&u1.x); q = __half22float2(*(__half2*)&u1.y);
            a1.x = fmaf(p.x, w1, a1.x); a1.y = fmaf(p.y, w1, a1.y);
            a1.z = fmaf(q.x, w1, a1.z); a1.w = fmaf(q.y, w1, a1.w);
            p = __half22float2(*(__half2*)&u2.x); q = __half22float2(*(__half2*)&u2.y);
            a2.x = fmaf(p.x, w2, a2.x); a2.y = fmaf(p.y, w2, a2.y);
            a2.z = fmaf(q.x, w2, a2.z); a2.w = fmaf(q.y, w2, a2.w);
            p = __half22float2(*(__half2*)&u3.x); q = __half22float2(*(__half2*)&u3.y);
            a3.x = fmaf(p.x, w3, a3.x); a3.y = fmaf(p.y, w3, a3.y);
            a3.z = fmaf(q.x, w3, a3.z); a3.w = fmaf(q.y, w3, a3.w);
        }
        for (; j < cnt; j++) {
            int   sj = __shfl_sync(~0u, s, j);
            float wj = __shfl_sync(~0u, w, j);
            uint2 u = *(const uint2*)&T16[(size_t)sj * 64 + lane * 2];
            float2 p = __half22float2(*(__half2*)&u.x);
            float2 q = __half22float2(*(__half2*)&u.y);
            a0.x = fmaf(p.x, wj, a0.x); a0.y = fmaf(p.y, wj, a0.y);
            a0.z = fmaf(q.x, wj, a0.z); a0.w = fmaf(q.y, wj, a0.w);
        }
    }
    float dd = dis[node], sn = dd * dd;
    uint2 ut = *(const uint2*)&T16[(size_t)node * 64 + lane * 2];
    float2 tp = __half22float2(*(__half2*)&ut.x);
    float2 tq = __half22float2(*(__half2*)&ut.y);
    float4 b = *(const float4*)&bias[lane * 4];
    float ox = fmaxf(a0.x + a1.x + a2.x + a3.x + tp.x * sn + b.x, 0.f);
    float oy = fmaxf(a0.y + a1.y + a2.y + a3.y + tp.y * sn + b.y, 0.f);
    float oz = fmaxf(a0.z + a1.z + a2.z + a3.z + tq.x * sn + b.z, 0.f);
    float ow = fmaxf(a0.w + a1.w + a2.w + a3.w + tq.y * sn + b.w, 0.f);
    OUT[(size_t)node * 64 + lane * 2]     = __floats2half2_rn(ox, oy);
    OUT[(size_t)node * 64 + lane * 2 + 1] = __floats2half2_rn(oz, ow);
}

__global__ void aggregate_lsm_kernel(const __half2* __restrict__ T16, const int* __restrict__ rp,
                                     const int* __restrict__ srcs, const float* __restrict__ ws,
                                     const float* __restrict__ dis, const float* __restrict__ bias,
                                     float* __restrict__ OUT, int n) {
    int node = blockIdx.x * 8 + (threadIdx.x >> 5);
    if (node >= n) return;
    int lane = threadIdx.x & 31;
    int beg = rp[node], end = rp[node + 1];

    float2 a0 = make_float2(0.f, 0.f), a1 = a0, a2 = a0, a3 = a0;
    for (int base = beg; base < end; base += 32) {
        int cnt = min(32, end - base);
        int s = 0; float w = 0.f;
        if (lane < cnt) { s = srcs[base + lane]; w = ws[base + lane]; }
        int j = 0;
        for (; j + 4 <= cnt; j += 4) {
            int   s0 = __shfl_sync(~0u, s, j),     s1 = __shfl_sync(~0u, s, j + 1);
            int   s2 = __shfl_sync(~0u, s, j + 2), s3 = __shfl_sync(~0u, s, j + 3);
            float w0 = __shfl_sync(~0u, w, j),     w1 = __shfl_sync(~0u, w, j + 1);
            float w2 = __shfl_sync(~0u, w, j + 2), w3 = __shfl_sync(~0u, w, j + 3);
            float2 v0 = __half22float2(T16[(size_t)s0 * 32 + lane]);
            float2 v1 = __half22float2(T16[(size_t)s1 * 32 + lane]);
            float2 v2 = __half22float2(T16[(size_t)s2 * 32 + lane]);
            float2 v3 = __half22float2(T16[(size_t)s3 * 32 + lane]);
            a0.x = fmaf(v0.x, w0, a0.x); a0.y = fmaf(v0.y, w0, a0.y);
            a1.x = fmaf(v1.x, w1, a1.x); a1.y = fmaf(v1.y, w1, a1.y);
            a2.x = fmaf(v2.x, w2, a2.x); a2.y = fmaf(v2.y, w2, a2.y);
            a3.x = fmaf(v3.x, w3, a3.x); a3.y = fmaf(v3.y, w3, a3.y);
        }
        for (; j < cnt; j++) {
            int   sj = __shfl_sync(~0u, s, j);
            float wj = __shfl_sync(~0u, w, j);
            float2 v = __half22float2(T16[(size_t)sj * 32 + lane]);
            a0.x = fmaf(v.x, wj, a0.x); a0.y = fmaf(v.y, wj, a0.y);
        }
    }
    float dd = dis[node], sn = dd * dd;
    float2 t = __half22float2(T16[(size_t)node * 32 + lane]);
    float2 b = *(const float2*)&bias[lane * 2];
    float vx = fmaxf(a0.x + a1.x + a2.x + a3.x + t.x * sn + b.x, 0.f);
    float vy = fmaxf(a0.y + a1.y + a2.y + a3.y + t.y * sn + b.y, 0.f);

    float m = fmaxf(vx, vy);
#pragma unroll
    for (int o = 16; o; o >>= 1) m = fmaxf(m, __shfl_xor_sync(~0u, m, o));
    float sum = expf(vx - m) + expf(vy - m);
#pragma unroll
    for (int o = 16; o; o >>= 1) sum += __shfl_xor_sync(~0u, sum, o);
    float lse = m + logf(sum);
    *(float2*)&OUT[(size_t)node * 64 + lane * 2] = make_float2(vx - lse, vy - lse);
}

// --------------------------------- driver -----------------------------------

extern "C" void kernel_launch(void* const* d_in, const int* in_sizes, int n_in,
                              void* d_out, int out_size) {
    const float* x  = (const float*)d_in[0];
    const int*   ei = (const int*)d_in[1];
    const float* W0 = (const float*)d_in[2];
    const float* b0 = (const float*)d_in[3];
    const float* W1 = (const float*)d_in[4];
    const float* b1 = (const float*)d_in[5];
    const float* W2 = (const float*)d_in[6];
    const float* b2 = (const float*)d_in[7];

    const int N = in_sizes[0] / 128;
    const int E = in_sizes[1] / 2;
    const int* src = ei;
    const int* dst = ei + E;

    __half2 *t16, *h16;
    float *dis, *ws;
    int *cnt, *rp, *cur, *srcs, *bsums;
    cudaGetSymbolAddress((void**)&t16,   g_t16);
    cudaGetSymbolAddress((void**)&h16,   g_h16);
    cudaGetSymbolAddress((void**)&dis,   g_dis);
    cudaGetSymbolAddress((void**)&cnt,   g_cnt);
    cudaGetSymbolAddress((void**)&rp,    g_rowptr);
    cudaGetSymbolAddress((void**)&cur,   g_cursor);
    cudaGetSymbolAddress((void**)&srcs,  g_srcs);
    cudaGetSymbolAddress((void**)&ws,    g_ws);
    cudaGetSymbolAddress((void**)&bsums, g_bsums);

    // smem: X 128x136 halves + W 128x72 halves = 34816 + 18432 = 53248 B
    const int smem_tc = (128 * 136 + 128 * 72) * 2;
    cudaFuncSetAttribute(gemm_tc<float, 128>,  cudaFuncAttributeMaxDynamicSharedMemorySize, smem_tc);
    cudaFuncSetAttribute(gemm_tc<__half, 128>, cudaFuncAttributeMaxDynamicSharedMemorySize, smem_tc);
    cudaFuncSetAttribute(gemm_tc<__half, 64>,  cudaFuncAttributeMaxDynamicSharedMemorySize, smem_tc);

    const int SB = (N + SCAN_CHUNK - 1) / SCAN_CHUNK;
    const int gblocks = (N + 127) / 128;
    const int ablocks = (N + 7) / 8;

    // launches 1-3: CSR front half
    zero_kernel<<<(N + 255) / 256, 256>>>(cnt, rp, cur, N);
    hist_kernel<<<(E + 255) / 256, 256>>>(dst, cnt, E);
    scan1_kernel<<<SB, SCAN_CHUNK>>>(cnt, rp, bsums, N);

    // launch 4 (ncu-profiled): layer-1 GEMM (fp32 input, converts in staging)
    gemm_tc<float, 128><<<dim3(gblocks, 2), 256, smem_tc>>>(x, W0, t16, N);

    // CSR back half
    dis_kernel<<<(N + 255) / 256, 256>>>(cnt, dis, N);
    scan3_kernel<<<SB, SCAN_CHUNK>>>(rp, cur, bsums, SB, N);
    bucket_kernel<<<(E + 255) / 256, 256>>>(src, dst, dis, cur, srcs, ws, E);

    // layer 1 aggregate -> h16 (fp16)
    aggregate128_kernel<<<ablocks, 256>>>(t16, rp, srcs, ws, dis, b0, h16, N);

    // layer 2 (fp16 input)
    gemm_tc<__half, 128><<<dim3(gblocks, 2), 256, smem_tc>>>((const __half*)h16, W1, t16, N);
    aggregate128_kernel<<<ablocks, 256>>>(t16, rp, srcs, ws, dis, b1, h16, N);

    // layer 3 + log_softmax
    gemm_tc<__half, 64><<<dim3(gblocks, 1), 256, smem_tc>>>((const __half*)h16, W2, t16, N);
    aggregate_lsm_kernel<<<ablocks, 256>>>(t16, rp, srcs, ws, dis, b2, (float*)d_out, N);
}

// round 14
// speedup vs baseline: 2.3902x; 1.0824x over previous
#include <cuda_runtime.h>
#include <cuda_fp16.h>
#include <cstdint>

// ---------------------------------------------------------------------------
// FCHCGNN: 3-layer GCN + log_softmax.
//   x pre-converted to fp16 once; CSR (counting sort by dst); per layer:
//   T = X@W on tensor cores (m16n8k16 f16xf16+f32, K=128 smem-resident,
//   full 128xFOUT tile per block, cp.async X staging), T fp16;
//   warp-per-node segment reduction (ILP 4, fp16 gathers, fp32 accum),
//   h fp16; final layer fuses log_softmax.
// ---------------------------------------------------------------------------

#define NN_MAX 100000
#define EE_MAX 1600000
#define SCAN_CHUNK 1024

__device__ __half2 g_x16[(size_t)NN_MAX * 64];
__device__ __half2 g_t16[(size_t)NN_MAX * 64];
__device__ __half2 g_h16[(size_t)NN_MAX * 64];
__device__ float   g_dis[NN_MAX];
__device__ int     g_cnt[NN_MAX];
__device__ int     g_rowptr[NN_MAX + 1];
__device__ int     g_cursor[NN_MAX + 1];
__device__ int     g_srcs[EE_MAX];
__device__ float   g_ws[EE_MAX];
__device__ int     g_bsums[128];

// --------------------------- cp.async helpers -------------------------------

__device__ __forceinline__ void cp_async16(unsigned saddr, const void* gptr, bool valid) {
    int sz = valid ? 16 : 0;
    asm volatile("cp.async.cg.shared.global [%0], [%1], 16, %2;\n"
                 :: "r"(saddr), "l"(gptr), "r"(sz));
}
__device__ __forceinline__ void cp_commit() {
    asm volatile("cp.async.commit_group;\n" ::: "memory");
}
__device__ __forceinline__ void cp_wait0() {
    asm volatile("cp.async.wait_group 0;\n" ::: "memory");
}

// --------------------------- x -> fp16 convert ------------------------------

__global__ void convert_x_kernel(const float* __restrict__ X, __half2* __restrict__ X16,
                                 int total4) {   // total4 = N*32 float4 chunks
    int i = blockIdx.x * blockDim.x + threadIdx.x;
    if (i < total4) {
        float4 v = *(const float4*)&X[(size_t)i * 4];
        X16[(size_t)i * 2]     = __floats2half2_rn(v.x, v.y);
        X16[(size_t)i * 2 + 1] = __floats2half2_rn(v.z, v.w);
    }
}

// --------------------------- CSR construction ------------------------------

__global__ void zero_kernel(int* __restrict__ cnt, int* __restrict__ rp,
                            int* __restrict__ cur, int n) {
    int i = blockIdx.x * blockDim.x + threadIdx.x;
    if (i < n) cnt[i] = 0;
    if (i == 0) { rp[0] = 0; cur[0] = 0; }
}

__global__ void hist_kernel(const int* __restrict__ dst, int* __restrict__ cnt, int e) {
    int i = blockIdx.x * blockDim.x + threadIdx.x;
    if (i < e) atomicAdd(&cnt[dst[i]], 1);
}

__global__ void scan1_kernel(const int* __restrict__ cnt, int* __restrict__ rp,
                             int* __restrict__ bsums, int m) {
    __shared__ int s[SCAN_CHUNK];
    int tid = threadIdx.x;
    int i = blockIdx.x * SCAN_CHUNK + tid;
    int v = (i < m) ? cnt[i] : 0;
    s[tid] = v;
    __syncthreads();
#pragma unroll
    for (int o = 1; o < SCAN_CHUNK; o <<= 1) {
        int t = 0;
        if (tid >= o) t = s[tid - o];
        __syncthreads();
        s[tid] += t;
        __syncthreads();
    }
    if (i < m) rp[i + 1] = s[tid];
    if (tid == SCAN_CHUNK - 1) bsums[blockIdx.x] = s[SCAN_CHUNK - 1];
}

__global__ void dis_kernel(const int* __restrict__ cnt, float* __restrict__ dis, int n) {
    int i = blockIdx.x * blockDim.x + threadIdx.x;
    if (i < n) dis[i] = rsqrtf((float)(cnt[i] + 1));
}

__global__ void scan3_kernel(int* __restrict__ rp, int* __restrict__ cur,
                             const int* __restrict__ bsums, int nb, int m) {
    __shared__ int sb[128];
    int t = threadIdx.x;
    if (t < 128) sb[t] = (t < nb) ? bsums[t] : 0;
    __syncthreads();
    int off = 0;
    for (int k = 0; k < blockIdx.x; k++) off += sb[k];
    int i = blockIdx.x * SCAN_CHUNK + t;
    if (i < m) {
        int v = rp[i + 1] + off;
        rp[i + 1] = v;
        cur[i + 1] = v;
    }
}

__global__ void bucket_kernel(const int* __restrict__ src, const int* __restrict__ dst,
                              const float* __restrict__ dis, int* __restrict__ cur,
                              int* __restrict__ srcs, float* __restrict__ ws, int e) {
    int i = blockIdx.x * blockDim.x + threadIdx.x;
    if (i < e) {
        int s = src[i], d = dst[i];
        int p = atomicAdd(&cur[d], 1);
        srcs[p] = s;
        ws[p] = dis[s] * dis[d];
    }
}

// ----------------------- tensor-core GEMM (HMMA) ----------------------------
// Block covers 128 rows x FOUT cols. FOUT=128: 16 warps (512 thr), FOUT=64:
// 8 warps (256 thr); warp tile 32x32 (wr = w&3, wc = w>>2).
// X fp16 staged via cp.async; W fp32->fp16 inline (L2-resident).

__device__ __forceinline__ void ldsm_x4(unsigned& r0, unsigned& r1, unsigned& r2,
                                        unsigned& r3, unsigned addr) {
    asm volatile("ldmatrix.sync.aligned.m8n8.x4.shared.b16 {%0,%1,%2,%3}, [%4];"
                 : "=r"(r0), "=r"(r1), "=r"(r2), "=r"(r3) : "r"(addr));
}
__device__ __forceinline__ void ldsm_x4t(unsigned& r0, unsigned& r1, unsigned& r2,
                                         unsigned& r3, unsigned addr) {
    asm volatile("ldmatrix.sync.aligned.m8n8.x4.trans.shared.b16 {%0,%1,%2,%3}, [%4];"
                 : "=r"(r0), "=r"(r1), "=r"(r2), "=r"(r3) : "r"(addr));
}
__device__ __forceinline__ void mma16816(float* c, unsigned a0, unsigned a1,
                                         unsigned a2, unsigned a3,
                                         unsigned b0, unsigned b1) {
    asm volatile("mma.sync.aligned.m16n8k16.row.col.f32.f16.f16.f32 "
                 "{%0,%1,%2,%3}, {%4,%5,%6,%7}, {%8,%9}, {%0,%1,%2,%3};"
                 : "+f"(c[0]), "+f"(c[1]), "+f"(c[2]), "+f"(c[3])
                 : "r"(a0), "r"(a1), "r"(a2), "r"(a3), "r"(b0), "r"(b1));
}

template <int FOUT>
__global__ void gemm_tc(const __half* __restrict__ X, const float* __restrict__ W,
                        __half2* __restrict__ T16, int n) {
    constexpr int AS = 136;            // X smem row stride (halves)
    constexpr int BS = FOUT + 8;       // W smem row stride (halves): 136 or 72
    constexpr int NT = (FOUT == 128) ? 512 : 256;
    extern __shared__ __half sm[];
    __half* Xs  = sm;                  // [128][AS]
    __half* Wsm = sm + 128 * AS;       // [128][BS]

    const int tid  = threadIdx.x;
    const int row0 = blockIdx.x * 128;

    unsigned xb = (unsigned)__cvta_generic_to_shared(Xs);
    unsigned wb = (unsigned)__cvta_generic_to_shared(Wsm);

    // ---- stage X via cp.async: 128 rows x 16 chunks of 16B ----
    for (int i = tid; i < 128 * 16; i += NT) {
        int r = i >> 4, c = i & 15;
        int gr = row0 + r;
        cp_async16(xb + (unsigned)(r * AS + c * 8) * 2u,
                   X + (size_t)gr * 128 + c * 8, gr < n);
    }
    cp_commit();
    // ---- stage W (fp32 -> fp16) ----
    for (int i = tid; i < 128 * (FOUT / 4); i += NT) {
        int k = i / (FOUT / 4), c = i % (FOUT / 4);
        float4 v = *(const float4*)&W[(size_t)k * FOUT + c * 4];
        __half2* p = (__half2*)&Wsm[k * BS + c * 4];
        p[0] = __floats2half2_rn(v.x, v.y);
        p[1] = __floats2half2_rn(v.z, v.w);
    }
    cp_wait0();
    __syncthreads();

    const int w    = tid >> 5;
    const int lane = tid & 31;
    const int wr   = w & 3;            // row group 0..3
    const int wc   = w >> 2;           // col group 0..(FOUT/32-1)

    float c[2][4][4];
#pragma unroll
    for (int ma = 0; ma < 2; ma++)
#pragma unroll
        for (int na = 0; na < 4; na++)
#pragma unroll
            for (int q = 0; q < 4; q++) c[ma][na][q] = 0.f;

    const int lrow = lane & 15;
    const int lhi  = (lane >> 4) << 3;

#pragma unroll
    for (int k0 = 0; k0 < 8; k0++) {
        unsigned a[2][4];
#pragma unroll
        for (int ma = 0; ma < 2; ma++) {
            unsigned addr = xb + (unsigned)((32 * wr + 16 * ma + lrow) * AS
                                            + k0 * 16 + lhi) * 2u;
            ldsm_x4(a[ma][0], a[ma][1], a[ma][2], a[ma][3], addr);
        }
        unsigned b[2][4];
#pragma unroll
        for (int np = 0; np < 2; np++) {
            unsigned addr = wb + (unsigned)((k0 * 16 + lrow) * BS
                                            + 32 * wc + 16 * np + lhi) * 2u;
            ldsm_x4t(b[np][0], b[np][1], b[np][2], b[np][3], addr);
        }
#pragma unroll
        for (int ma = 0; ma < 2; ma++)
#pragma unroll
            for (int np = 0; np < 2; np++)
#pragma unroll
                for (int nb = 0; nb < 2; nb++)
                    mma16816(c[ma][2 * np + nb], a[ma][0], a[ma][1], a[ma][2],
                             a[ma][3], b[np][2 * nb], b[np][2 * nb + 1]);
    }

    const int g  = lane >> 2;
    const int lc = lane & 3;
#pragma unroll
    for (int ma = 0; ma < 2; ma++) {
        int r0 = row0 + 32 * wr + 16 * ma + g;
#pragma unroll
        for (int na = 0; na < 4; na++) {
            int h2i = 16 * wc + 4 * na + lc;
            if (r0 < n)
                T16[(size_t)r0 * (FOUT / 2) + h2i] =
                    __floats2half2_rn(c[ma][na][0], c[ma][na][1]);
            if (r0 + 8 < n)
                T16[(size_t)(r0 + 8) * (FOUT / 2) + h2i] =
                    __floats2half2_rn(c[ma][na][2], c[ma][na][3]);
        }
    }
}

// ---------------------- warp-per-node segment reduction ---------------------

__global__ void aggregate128_kernel(const __half2* __restrict__ T16, const int* __restrict__ rp,
                                    const int* __restrict__ srcs, const float* __restrict__ ws,
                                    const float* __restrict__ dis, const float* __restrict__ bias,
                                    __half2* __restrict__ OUT, int n) {
    int node = blockIdx.x * 8 + (threadIdx.x >> 5);
    if (node >= n) return;
    int lane = threadIdx.x & 31;
    int beg = rp[node], end = rp[node + 1];

    float4 a0 = make_float4(0.f, 0.f, 0.f, 0.f), a1 = a0, a2 = a0, a3 = a0;
    for (int base = beg; base < end; base += 32) {
        int cnt = min(32, end - base);
        int s = 0; float w = 0.f;
        if (lane < cnt) { s = srcs[base + lane]; w = ws[base + lane]; }
        int j = 0;
        for (; j + 4 <= cnt; j += 4) {
            int   s0 = __shfl_sync(~0u, s, j),     s1 = __shfl_sync(~0u, s, j + 1);
            int   s2 = __shfl_sync(~0u, s, j + 2), s3 = __shfl_sync(~0u, s, j + 3);
            float w0 = __shfl_sync(~0u, w, j),     w1 = __shfl_sync(~0u, w, j + 1);
            float w2 = __shfl_sync(~0u, w, j + 2), w3 = __shfl_sync(~0u, w, j + 3);
            uint2 u0 = *(const uint2*)&T16[(size_t)s0 * 64 + lane * 2];
            uint2 u1 = *(const uint2*)&T16[(size_t)s1 * 64 + lane * 2];
            uint2 u2 = *(const uint2*)&T16[(size_t)s2 * 64 + lane * 2];
            uint2 u3 = *(const uint2*)&T16[(size_t)s3 * 64 + lane * 2];
            float2 p, q;
            p = __half22float2(*(__half2*)&u0.x); q = __half22float2(*(__half2*)&u0.y);
            a0.x = fmaf(p.x, w0, a0.x); a0.y = fmaf(p.y, w0, a0.y);
            a0.z = fmaf(q.x, w0, a0.z); a0.w = fmaf(q.y, w0, a0.w);
            p = __half22float2(*(__half2*)&u1.x); q = __half22float2(*(__half2*)&u1.y);
            a1.x = fmaf(p.x, w1, a1.x); a1.y = fmaf(p.y, w1, a1.y);
            a1.z = fmaf(q.x, w1, a1.z); a1.w = fmaf(q.y, w1, a1.w);
            p = __half22float2(*(__half2*)&u2.x); q = __half22float2(*(__half2*)&u2.y);
            a2.x = fmaf(p.x, w2, a2.x); a2.y = fmaf(p.y, w2, a2.y);
            a2.z = fmaf(q.x, w2, a2.z); a2.w = fmaf(q.y, w2, a2.w);
            p = __half22float2(*(__half2*)&u3.x); q = __half22float2(*(__half2*)&u3.y);
            a3.x = fmaf(p.x, w3, a3.x); a3.y = fmaf(p.y, w3, a3.y);
            a3.z = fmaf(q.x, w3, a3.z); a3.w = fmaf(q.y, w3, a3.w);
        }
        for (; j < cnt; j++) {
            int   sj = __shfl_sync(~0u, s, j);
            float wj = __shfl_sync(~0u, w, j);
            uint2 u = *(const uint2*)&T16[(size_t)sj * 64 + lane * 2];
            float2 p = __half22float2(*(__half2*)&u.x);
            float2 q = __half22float2(*(__half2*)&u.y);
            a0.x = fmaf(p.x, wj, a0.x); a0.y = fmaf(p.y, wj, a0.y);
            a0.z = fmaf(q.x, wj, a0.z); a0.w = fmaf(q.y, wj, a0.w);
        }
    }
    float dd = dis[node], sn = dd * dd;
    uint2 ut = *(const uint2*)&T16[(size_t)node * 64 + lane * 2];
    float2 tp = __half22float2(*(__half2*)&ut.x);
    float2 tq = __half22float2(*(__half2*)&ut.y);
    float4 b = *(const float4*)&bias[lane * 4];
    float ox = fmaxf(a0.x + a1.x + a2.x + a3.x + tp.x * sn + b.x, 0.f);
    float oy = fmaxf(a0.y + a1.y + a2.y + a3.y + tp.y * sn + b.y, 0.f);
    float oz = fmaxf(a0.z + a1.z + a2.z + a3.z + tq.x * sn + b.z, 0.f);
    float ow = fmaxf(a0.w + a1.w + a2.w + a3.w + tq.y * sn + b.w, 0.f);
    OUT[(size_t)node * 64 + lane * 2]     = __floats2half2_rn(ox, oy);
    OUT[(size_t)node * 64 + lane * 2 + 1] = __floats2half2_rn(oz, ow);
}

__global__ void aggregate_lsm_kernel(const __half2* __restrict__ T16, const int* __restrict__ rp,
                                     const int* __restrict__ srcs, const float* __restrict__ ws,
                                     const float* __restrict__ dis, const float* __restrict__ bias,
                                     float* __restrict__ OUT, int n) {
    int node = blockIdx.x * 8 + (threadIdx.x >> 5);
    if (node >= n) return;
    int lane = threadIdx.x & 31;
    int beg = rp[node], end = rp[node + 1];

    float2 a0 = make_float2(0.f, 0.f), a1 = a0, a2 = a0, a3 = a0;
    for (int base = beg; base < end; base += 32) {
        int cnt = min(32, end - base);
        int s = 0; float w = 0.f;
        if (lane < cnt) { s = srcs[base + lane]; w = ws[base + lane]; }
        int j = 0;
        for (; j + 4 <= cnt; j += 4) {
            int   s0 = __shfl_sync(~0u, s, j),     s1 = __shfl_sync(~0u, s, j + 1);
            int   s2 = __shfl_sync(~0u, s, j + 2), s3 = __shfl_sync(~0u, s, j + 3);
            float w0 = __shfl_sync(~0u, w, j),     w1 = __shfl_sync(~0u, w, j + 1);
            float w2 = __shfl_sync(~0u, w, j + 2), w3 = __shfl_sync(~0u, w, j + 3);
            float2 v0 = __half22float2(T16[(size_t)s0 * 32 + lane]);
            float2 v1 = __half22float2(T16[(size_t)s1 * 32 + lane]);
            float2 v2 = __half22float2(T16[(size_t)s2 * 32 + lane]);
            float2 v3 = __half22float2(T16[(size_t)s3 * 32 + lane]);
            a0.x = fmaf(v0.x, w0, a0.x); a0.y = fmaf(v0.y, w0, a0.y);
            a1.x = fmaf(v1.x, w1, a1.x); a1.y = fmaf(v1.y, w1, a1.y);
            a2.x = fmaf(v2.x, w2, a2.x); a2.y = fmaf(v2.y, w2, a2.y);
            a3.x = fmaf(v3.x, w3, a3.x); a3.y = fmaf(v3.y, w3, a3.y);
        }
        for (; j < cnt; j++) {
            int   sj = __shfl_sync(~0u, s, j);
            float wj = __shfl_sync(~0u, w, j);
            float2 v = __half22float2(T16[(size_t)sj * 32 + lane]);
            a0.x = fmaf(v.x, wj, a0.x); a0.y = fmaf(v.y, wj, a0.y);
        }
    }
    float dd = dis[node], sn = dd * dd;
    float2 t = __half22float2(T16[(size_t)node * 32 + lane]);
    float2 b = *(const float2*)&bias[lane * 2];
    float vx = fmaxf(a0.x + a1.x + a2.x + a3.x + t.x * sn + b.x, 0.f);
    float vy = fmaxf(a0.y + a1.y + a2.y + a3.y + t.y * sn + b.y, 0.f);

    float m = fmaxf(vx, vy);
#pragma unroll
    for (int o = 16; o; o >>= 1) m = fmaxf(m, __shfl_xor_sync(~0u, m, o));
    float sum = expf(vx - m) + expf(vy - m);
#pragma unroll
    for (int o = 16; o; o >>= 1) sum += __shfl_xor_sync(~0u, sum, o);
    float lse = m + logf(sum);
    *(float2*)&OUT[(size_t)node * 64 + lane * 2] = make_float2(vx - lse, vy - lse);
}

// --------------------------------- driver -----------------------------------

extern "C" void kernel_launch(void* const* d_in, const int* in_sizes, int n_in,
                              void* d_out, int out_size) {
    const float* x  = (const float*)d_in[0];
    const int*   ei = (const int*)d_in[1];
    const float* W0 = (const float*)d_in[2];
    const float* b0 = (const float*)d_in[3];
    const float* W1 = (const float*)d_in[4];
    const float* b1 = (const float*)d_in[5];
    const float* W2 = (const float*)d_in[6];
    const float* b2 = (const float*)d_in[7];

    const int N = in_sizes[0] / 128;
    const int E = in_sizes[1] / 2;
    const int* src = ei;
    const int* dst = ei + E;

    __half2 *x16, *t16, *h16;
    float *dis, *ws;
    int *cnt, *rp, *cur, *srcs, *bsums;
    cudaGetSymbolAddress((void**)&x16,   g_x16);
    cudaGetSymbolAddress((void**)&t16,   g_t16);
    cudaGetSymbolAddress((void**)&h16,   g_h16);
    cudaGetSymbolAddress((void**)&dis,   g_dis);
    cudaGetSymbolAddress((void**)&cnt,   g_cnt);
    cudaGetSymbolAddress((void**)&rp,    g_rowptr);
    cudaGetSymbolAddress((void**)&cur,   g_cursor);
    cudaGetSymbolAddress((void**)&srcs,  g_srcs);
    cudaGetSymbolAddress((void**)&ws,    g_ws);
    cudaGetSymbolAddress((void**)&bsums, g_bsums);

    const int smem128 = (128 * 136 + 128 * 136) * 2;  // 69632 B
    const int smem64  = (128 * 136 + 128 * 72) * 2;   // 53248 B
    cudaFuncSetAttribute(gemm_tc<128>, cudaFuncAttributeMaxDynamicSharedMemorySize, smem128);
    cudaFuncSetAttribute(gemm_tc<64>,  cudaFuncAttributeMaxDynamicSharedMemorySize, smem64);

    const int SB = (N + SCAN_CHUNK - 1) / SCAN_CHUNK;
    const int gblocks = (N + 127) / 128;
    const int ablocks = (N + 7) / 8;

    // launches 1-3
    convert_x_kernel<<<(N * 32 + 255) / 256, 256>>>(x, x16, N * 32);
    zero_kernel<<<(N + 255) / 256, 256>>>(cnt, rp, cur, N);
    hist_kernel<<<(E + 255) / 256, 256>>>(dst, cnt, E);

    // launch 4 (ncu-profiled): layer-1 GEMM
    gemm_tc<128><<<gblocks, 512, smem128>>>((const __half*)x16, W0, t16, N);

    // CSR back half
    scan1_kernel<<<SB, SCAN_CHUNK>>>(cnt, rp, bsums, N);
    dis_kernel<<<(N + 255) / 256, 256>>>(cnt, dis, N);
    scan3_kernel<<<SB, SCAN_CHUNK>>>(rp, cur, bsums, SB, N);
    bucket_kernel<<<(E + 255) / 256, 256>>>(src, dst, dis, cur, srcs, ws, E);

    // layer 1 aggregate -> h16
    aggregate128_kernel<<<ablocks, 256>>>(t16, rp, srcs, ws, dis, b0, h16, N);

    // layer 2
    gemm_tc<128><<<gblocks, 512, smem128>>>((const __half*)h16, W1, t16, N);
    aggregate128_kernel<<<ablocks, 256>>>(t16, rp, srcs, ws, dis, b1, h16, N);

    // layer 3 + log_softmax
    gemm_tc<64><<<gblocks, 256, smem64>>>((const __half*)h16, W2, t16, N);
    aggregate_lsm_kernel<<<ablocks, 256>>>(t16, rp, srcs, ws, dis, b2, (float*)d_out, N);
}